// round 3
// baseline (speedup 1.0000x reference)
#include <cuda_runtime.h>
#include <math.h>

#define BATCH 4
#define SEQ   2048
#define DMODEL 1024
#define NH    16
#define DK    64
#define MROWS (BATCH*SEQ)   // 8192

// Scratch (no allocation allowed anywhere) — Q/K/V in [B,H,S,DK], ctx in [B,S,H*DK]
__device__ __align__(256) float g_Q[BATCH*NH*SEQ*DK];
__device__ __align__(256) float g_K[BATCH*NH*SEQ*DK];
__device__ __align__(256) float g_V[BATCH*NH*SEQ*DK];
__device__ __align__(256) float g_C[BATCH*SEQ*NH*DK];

// ---------------------------------------------------------------------------
// XOR swizzle for 64x64 fp32 tiles (pitch 64 floats, 16 groups of 4 floats).
// Conflict-free LDS.128 for row-major reads, strided-row reads, P stores.
// ---------------------------------------------------------------------------
__device__ __forceinline__ int swz(int r, int c) {
    return (r << 6) + ((((c >> 2) ^ (r >> 2)) & 15) << 2) + (c & 3);
}

// ---------------------------------------------------------------------------
// QKV projection: q/k/v = x @ W[h] + b[h]
// grid (MROWS/64, NH, 3), block 256 (16x16 threads, 4x4 micro-tile)
// ---------------------------------------------------------------------------
__global__ void __launch_bounds__(256) qkv_proj(
    const float* __restrict__ x,
    const float* __restrict__ Wq, const float* __restrict__ bq,
    const float* __restrict__ Wk, const float* __restrict__ bk,
    const float* __restrict__ Wv, const float* __restrict__ bv)
{
    __shared__ __align__(16) float As[32][68];   // As[k][row]  (x tile, transposed)
    __shared__ __align__(16) float Bs[32][68];   // Bs[k][col]  (W tile)

    const int mt = blockIdx.x, h = blockIdx.y, mat = blockIdx.z;
    const float* W; const float* bias; float* outp;
    if (mat == 0)      { W = Wq; bias = bq; outp = g_Q; }
    else if (mat == 1) { W = Wk; bias = bk; outp = g_K; }
    else               { W = Wv; bias = bv; outp = g_V; }
    W    += (size_t)h * DMODEL * DK;
    bias += h * DK;

    const int tid = threadIdx.x;
    const int tx = tid & 15, ty = tid >> 4;
    const int row0 = mt * 64;

    float acc[4][4] = {};

    for (int k0 = 0; k0 < DMODEL; k0 += 32) {
        #pragma unroll
        for (int l = 0; l < 2; l++) {               // x tile 64 rows x 32 k
            int idx = tid + l * 256;                // 512 float4 slots
            int r  = idx >> 3;
            int kk = (idx & 7) << 2;
            float4 v = *(const float4*)(x + (size_t)(row0 + r) * DMODEL + k0 + kk);
            As[kk + 0][r] = v.x; As[kk + 1][r] = v.y;
            As[kk + 2][r] = v.z; As[kk + 3][r] = v.w;
        }
        #pragma unroll
        for (int l = 0; l < 2; l++) {               // W tile 32 k x 64 n
            int idx = tid + l * 256;
            int dd = idx >> 4;
            int nn = (idx & 15) << 2;
            *(float4*)&Bs[dd][nn] = *(const float4*)(W + (size_t)(k0 + dd) * DK + nn);
        }
        __syncthreads();
        #pragma unroll
        for (int kk = 0; kk < 32; kk++) {
            float4 a = *(const float4*)&As[kk][ty << 2];
            float4 b = *(const float4*)&Bs[kk][tx << 2];
            float av[4] = {a.x, a.y, a.z, a.w};
            float bv4[4] = {b.x, b.y, b.z, b.w};
            #pragma unroll
            for (int i = 0; i < 4; i++)
                #pragma unroll
                for (int j = 0; j < 4; j++)
                    acc[i][j] += av[i] * bv4[j];
        }
        __syncthreads();
    }

    // epilogue: bias + scatter into [B,H,S,DK]
    const int bi = row0 / SEQ;
    const int s0 = row0 % SEQ;
    float bvals[4];
    #pragma unroll
    for (int j = 0; j < 4; j++) bvals[j] = bias[(tx << 2) + j];
    float* obase = outp + ((size_t)(bi * NH + h) * SEQ) * DK;
    #pragma unroll
    for (int i = 0; i < 4; i++) {
        int s = s0 + (ty << 2) + i;
        float4 v = make_float4(acc[i][0] + bvals[0], acc[i][1] + bvals[1],
                               acc[i][2] + bvals[2], acc[i][3] + bvals[3]);
        *(float4*)(obase + (size_t)s * DK + (tx << 2)) = v;
    }
}

// ---------------------------------------------------------------------------
// Causal flash attention, fp32. grid (SEQ/64, BATCH*NH), block 256, 64KB smem.
// ---------------------------------------------------------------------------
__global__ void __launch_bounds__(256) attn_flash()
{
    extern __shared__ __align__(16) float sm[];
    float* Qs = sm;              // 64x64
    float* Ks = sm + 4096;
    float* Vs = sm + 8192;
    float* Ps = sm + 12288;

    const int qt  = blockIdx.x;
    const int bh  = blockIdx.y;
    const int tid = threadIdx.x;
    const int tx = tid & 15, ty = tid >> 4;

    const float* Qg = g_Q + (size_t)bh * SEQ * DK + (size_t)qt * 64 * DK;
    const float* Kg = g_K + (size_t)bh * SEQ * DK;
    const float* Vg = g_V + (size_t)bh * SEQ * DK;

    const float scale = 0.125f;   // 1/sqrt(64)

    // Load Q tile (pre-scaled)
    #pragma unroll
    for (int l = 0; l < 4; l++) {
        int idx = tid + l * 256;            // 1024 float4 slots
        int r = idx >> 4;
        int c = (idx & 15) << 2;
        float4 v = *(const float4*)(Qg + (size_t)r * DK + c);
        v.x *= scale; v.y *= scale; v.z *= scale; v.w *= scale;
        *(float4*)&Qs[swz(r, c)] = v;
    }

    float m_i[4] = {-INFINITY, -INFINITY, -INFINITY, -INFINITY};
    float l_i[4] = {0.f, 0.f, 0.f, 0.f};
    float o[4][4] = {};

    for (int j = 0; j <= qt; j++) {
        // Load K,V tiles for this step
        #pragma unroll
        for (int l = 0; l < 4; l++) {
            int idx = tid + l * 256;
            int r = idx >> 4;
            int c = (idx & 15) << 2;
            *(float4*)&Ks[swz(r, c)] = *(const float4*)(Kg + (size_t)(j * 64 + r) * DK + c);
            *(float4*)&Vs[swz(r, c)] = *(const float4*)(Vg + (size_t)(j * 64 + r) * DK + c);
        }
        __syncthreads();

        // S = (Q * scale) K^T
        float s[4][4] = {};
        #pragma unroll
        for (int d = 0; d < DK; d += 4) {
            float4 a[4], b[4];
            #pragma unroll
            for (int i = 0; i < 4; i++)  a[i] = *(const float4*)&Qs[swz((ty << 2) + i, d)];
            #pragma unroll
            for (int jj = 0; jj < 4; jj++) b[jj] = *(const float4*)&Ks[swz((tx << 2) + jj, d)];
            #pragma unroll
            for (int i = 0; i < 4; i++)
                #pragma unroll
                for (int jj = 0; jj < 4; jj++)
                    s[i][jj] += a[i].x * b[jj].x + a[i].y * b[jj].y
                              + a[i].z * b[jj].z + a[i].w * b[jj].w;
        }

        // causal mask on diagonal tile
        if (j == qt) {
            #pragma unroll
            for (int i = 0; i < 4; i++)
                #pragma unroll
                for (int jj = 0; jj < 4; jj++)
                    if (((tx << 2) + jj) > ((ty << 2) + i)) s[i][jj] = -INFINITY;
        }

        // online softmax (rows owned by 16-lane tx groups)
        #pragma unroll
        for (int i = 0; i < 4; i++) {
            float rm = fmaxf(fmaxf(s[i][0], s[i][1]), fmaxf(s[i][2], s[i][3]));
            #pragma unroll
            for (int off = 1; off < 16; off <<= 1)
                rm = fmaxf(rm, __shfl_xor_sync(0xffffffffu, rm, off));
            float mnew = fmaxf(m_i[i], rm);
            float corr = __expf(m_i[i] - mnew);
            m_i[i] = mnew;
            float4 p;
            p.x = __expf(s[i][0] - mnew); p.y = __expf(s[i][1] - mnew);
            p.z = __expf(s[i][2] - mnew); p.w = __expf(s[i][3] - mnew);
            float rs = p.x + p.y + p.z + p.w;
            #pragma unroll
            for (int off = 1; off < 16; off <<= 1)
                rs += __shfl_xor_sync(0xffffffffu, rs, off);
            l_i[i] = l_i[i] * corr + rs;
            o[i][0] *= corr; o[i][1] *= corr; o[i][2] *= corr; o[i][3] *= corr;
            *(float4*)&Ps[swz((ty << 2) + i, tx << 2)] = p;
        }
        __syncthreads();

        // O += P @ V
        #pragma unroll
        for (int kk = 0; kk < 64; kk += 4) {
            float4 a[4], b[4];
            #pragma unroll
            for (int i = 0; i < 4; i++) a[i] = *(const float4*)&Ps[swz((ty << 2) + i, kk)];
            #pragma unroll
            for (int t = 0; t < 4; t++) b[t] = *(const float4*)&Vs[swz(kk + t, tx << 2)];
            #pragma unroll
            for (int i = 0; i < 4; i++) {
                o[i][0] += a[i].x * b[0].x + a[i].y * b[1].x + a[i].z * b[2].x + a[i].w * b[3].x;
                o[i][1] += a[i].x * b[0].y + a[i].y * b[1].y + a[i].z * b[2].y + a[i].w * b[3].y;
                o[i][2] += a[i].x * b[0].z + a[i].y * b[1].z + a[i].z * b[2].z + a[i].w * b[3].z;
                o[i][3] += a[i].x * b[0].w + a[i].y * b[1].w + a[i].z * b[2].w + a[i].w * b[3].w;
            }
        }
        __syncthreads();
    }

    // normalize + write ctx in [B, S, H*DK] (head-concat layout)
    const int b_idx = bh / NH, h = bh % NH;
    #pragma unroll
    for (int i = 0; i < 4; i++) {
        float inv = 1.0f / l_i[i];
        int srow = qt * 64 + (ty << 2) + i;
        float4 v = make_float4(o[i][0] * inv, o[i][1] * inv, o[i][2] * inv, o[i][3] * inv);
        *(float4*)(g_C + (size_t)(b_idx * SEQ + srow) * DMODEL + h * DK + (tx << 2)) = v;
    }
}

// ---------------------------------------------------------------------------
// Output projection: out = ctx @ Wo + bo.  grid (MROWS/64, DMODEL/64), block 256
// ---------------------------------------------------------------------------
__global__ void __launch_bounds__(256) out_proj(
    const float* __restrict__ Wo, const float* __restrict__ bo,
    float* __restrict__ out)
{
    __shared__ __align__(16) float As[32][68];
    __shared__ __align__(16) float Bs[32][68];

    const int mt = blockIdx.x, nt = blockIdx.y;
    const int tid = threadIdx.x;
    const int tx = tid & 15, ty = tid >> 4;
    const int row0 = mt * 64, n0 = nt * 64;

    float acc[4][4] = {};

    for (int k0 = 0; k0 < DMODEL; k0 += 32) {
        #pragma unroll
        for (int l = 0; l < 2; l++) {
            int idx = tid + l * 256;
            int r  = idx >> 3;
            int kk = (idx & 7) << 2;
            float4 v = *(const float4*)(g_C + (size_t)(row0 + r) * DMODEL + k0 + kk);
            As[kk + 0][r] = v.x; As[kk + 1][r] = v.y;
            As[kk + 2][r] = v.z; As[kk + 3][r] = v.w;
        }
        #pragma unroll
        for (int l = 0; l < 2; l++) {
            int idx = tid + l * 256;
            int dd = idx >> 4;
            int nn = (idx & 15) << 2;
            *(float4*)&Bs[dd][nn] = *(const float4*)(Wo + (size_t)(k0 + dd) * DMODEL + n0 + nn);
        }
        __syncthreads();
        #pragma unroll
        for (int kk = 0; kk < 32; kk++) {
            float4 a = *(const float4*)&As[kk][ty << 2];
            float4 b = *(const float4*)&Bs[kk][tx << 2];
            float av[4] = {a.x, a.y, a.z, a.w};
            float bv4[4] = {b.x, b.y, b.z, b.w};
            #pragma unroll
            for (int i = 0; i < 4; i++)
                #pragma unroll
                for (int j = 0; j < 4; j++)
                    acc[i][j] += av[i] * bv4[j];
        }
        __syncthreads();
    }

    float bvals[4];
    #pragma unroll
    for (int j = 0; j < 4; j++) bvals[j] = bo[n0 + (tx << 2) + j];
    #pragma unroll
    for (int i = 0; i < 4; i++) {
        int r = row0 + (ty << 2) + i;
        float4 v = make_float4(acc[i][0] + bvals[0], acc[i][1] + bvals[1],
                               acc[i][2] + bvals[2], acc[i][3] + bvals[3]);
        *(float4*)(out + (size_t)r * DMODEL + n0 + (tx << 2)) = v;
    }
}

// ---------------------------------------------------------------------------
extern "C" void kernel_launch(void* const* d_in, const int* in_sizes, int n_in,
                              void* d_out, int out_size)
{
    const float* x  = (const float*)d_in[0];
    const float* Wq = (const float*)d_in[1];
    const float* bq = (const float*)d_in[2];
    const float* Wk = (const float*)d_in[3];
    const float* bk = (const float*)d_in[4];
    const float* Wv = (const float*)d_in[5];
    const float* bv = (const float*)d_in[6];
    const float* Wo = (const float*)d_in[7];
    const float* bo = (const float*)d_in[8];
    float* out = (float*)d_out;

    // host-side attribute set (not a stream op; safe under graph capture)
    cudaFuncSetAttribute(attn_flash, cudaFuncAttributeMaxDynamicSharedMemorySize, 65536);

    qkv_proj<<<dim3(MROWS / 64, NH, 3), 256>>>(x, Wq, bq, Wk, bk, Wv, bv);
    attn_flash<<<dim3(SEQ / 64, BATCH * NH), 256, 65536>>>();
    out_proj<<<dim3(MROWS / 64, DMODEL / 64), 256>>>(Wo, bo, out);
}

// round 5
// speedup vs baseline: 5.2533x; 5.2533x over previous
#include <cuda_runtime.h>
#include <math.h>

#define BATCH 4
#define SEQ   2048
#define DMODEL 1024
#define NH    16
#define DK    64
#define MROWS (BATCH*SEQ)   // 8192

// Scratch — Q/K/V in [B,H,S,DK], ctx in [B,S,H*DK]
__device__ __align__(256) float g_Q[BATCH*NH*SEQ*DK];
__device__ __align__(256) float g_K[BATCH*NH*SEQ*DK];
__device__ __align__(256) float g_V[BATCH*NH*SEQ*DK];
__device__ __align__(256) float g_C[BATCH*SEQ*NH*DK];

// ---------------------------------------------------------------------------
// tf32 helpers
// ---------------------------------------------------------------------------
__device__ __forceinline__ float to_tf32(float x) {
    float y;
    asm("cvt.rna.tf32.f32 %0, %1;" : "=f"(y) : "f"(x));
    return y;
}

__device__ __forceinline__ void mma_tf32(float d[4], const unsigned a[4], const unsigned b[2]) {
    asm volatile(
        "mma.sync.aligned.m16n8k8.row.col.f32.tf32.tf32.f32 "
        "{%0,%1,%2,%3}, {%4,%5,%6,%7}, {%8,%9}, {%0,%1,%2,%3};"
        : "+f"(d[0]), "+f"(d[1]), "+f"(d[2]), "+f"(d[3])
        : "r"(a[0]), "r"(a[1]), "r"(a[2]), "r"(a[3]), "r"(b[0]), "r"(b[1]));
}

__device__ __forceinline__ unsigned fu(float x) { return __float_as_uint(x); }

// Fragment pitches (floats):
//  A-frag pattern (l>>2)*P + (l&3): conflict-free iff P % 32 == 4
//     width 32 tiles -> P = 36;  width 64 tiles -> P = 68
//  B-frag pattern (l&3)*P + (l>>2): conflict-free iff P % 32 == 8 -> P = 72
#define PA 36
#define PQ 68
#define PB 72

// ---------------------------------------------------------------------------
// QKV projection: grid (MROWS/128, NH, 3), block 256. Tile 128x64, 8 warps.
// ---------------------------------------------------------------------------
__global__ void __launch_bounds__(256) qkv_proj(
    const float* __restrict__ x,
    const float* __restrict__ Wq, const float* __restrict__ bq,
    const float* __restrict__ Wk, const float* __restrict__ bk,
    const float* __restrict__ Wv, const float* __restrict__ bv)
{
    __shared__ float As[128 * PA];   // 128 rows x 32 k  (pitch 36)
    __shared__ float Bs[32 * PB];    // 32 k x 64 n      (pitch 72)

    const int mt = blockIdx.x, h = blockIdx.y, mat = blockIdx.z;
    const float* W; const float* bias; float* outp;
    if (mat == 0)      { W = Wq; bias = bq; outp = g_Q; }
    else if (mat == 1) { W = Wk; bias = bk; outp = g_K; }
    else               { W = Wv; bias = bv; outp = g_V; }
    W    += (size_t)h * DMODEL * DK;
    bias += h * DK;

    const int tid = threadIdx.x;
    const int w  = tid >> 5;
    const int l  = tid & 31;
    const int lq = l >> 2, lr = l & 3;
    const int wm = w >> 1, wn = w & 1;       // warp grid 4 x 2
    const int row0 = mt * 128;

    float acc[2][4][4] = {};

    for (int k0 = 0; k0 < DMODEL; k0 += 32) {
        #pragma unroll
        for (int i = 0; i < 4; i++) {
            int idx = tid + i * 256;             // 1024 float4 slots
            int r = idx >> 3, kk = (idx & 7) << 2;
            float4 v = *(const float4*)(x + (size_t)(row0 + r) * DMODEL + k0 + kk);
            v.x = to_tf32(v.x); v.y = to_tf32(v.y);
            v.z = to_tf32(v.z); v.w = to_tf32(v.w);
            *(float4*)&As[r * PA + kk] = v;
        }
        #pragma unroll
        for (int i = 0; i < 2; i++) {
            int idx = tid + i * 256;             // 512 float4 slots
            int kr = idx >> 4, nn = (idx & 15) << 2;
            float4 v = *(const float4*)(W + (size_t)(k0 + kr) * DK + nn);
            v.x = to_tf32(v.x); v.y = to_tf32(v.y);
            v.z = to_tf32(v.z); v.w = to_tf32(v.w);
            *(float4*)&Bs[kr * PB + nn] = v;
        }
        __syncthreads();

        #pragma unroll
        for (int kk = 0; kk < 4; kk++) {
            unsigned a[2][4], b[4][2];
            #pragma unroll
            for (int mi = 0; mi < 2; mi++) {
                int base = (wm * 32 + mi * 16 + lq) * PA + kk * 8 + lr;
                a[mi][0] = fu(As[base]);
                a[mi][1] = fu(As[base + 8 * PA]);
                a[mi][2] = fu(As[base + 4]);
                a[mi][3] = fu(As[base + 8 * PA + 4]);
            }
            #pragma unroll
            for (int ni = 0; ni < 4; ni++) {
                int base = (kk * 8 + lr) * PB + wn * 32 + ni * 8 + lq;
                b[ni][0] = fu(Bs[base]);
                b[ni][1] = fu(Bs[base + 4 * PB]);
            }
            #pragma unroll
            for (int mi = 0; mi < 2; mi++)
                #pragma unroll
                for (int ni = 0; ni < 4; ni++)
                    mma_tf32(acc[mi][ni], a[mi], b[ni]);
        }
        __syncthreads();
    }

    // epilogue: bias + scatter into [B,H,S,DK]
    #pragma unroll
    for (int mi = 0; mi < 2; mi++)
        #pragma unroll
        for (int rh = 0; rh < 2; rh++) {
            int m = row0 + wm * 32 + mi * 16 + lq + rh * 8;
            int bi = m >> 11, s = m & (SEQ - 1);
            float* ob = outp + ((size_t)(bi * NH + h) * SEQ + s) * DK;
            #pragma unroll
            for (int ni = 0; ni < 4; ni++) {
                int col = wn * 32 + ni * 8 + 2 * lr;
                float2 bv = *(const float2*)(bias + col);
                float2 v = make_float2(acc[mi][ni][rh * 2 + 0] + bv.x,
                                       acc[mi][ni][rh * 2 + 1] + bv.y);
                *(float2*)(ob + col) = v;
            }
        }
}

// ---------------------------------------------------------------------------
// Causal flash attention, tf32 MMA core. grid (SEQ/64, BATCH*NH), block 128.
// 4 warps, warp tile 16x64. Dynamic smem (70,656 B).
// ---------------------------------------------------------------------------
#define ATTN_SMEM ((3 * 64 * PQ + 64 * PB) * 4)

__global__ void __launch_bounds__(128) attn_flash()
{
    extern __shared__ __align__(16) float sm[];
    float* Qs = sm;                    // [q][dk]  64 x pitch 68 (A-frag)
    float* Ks = sm + 64 * PQ;          // [s][dk]  64 x pitch 68 (B-frag for S)
    float* Ps = sm + 2 * 64 * PQ;      // [q][s]   64 x pitch 68 (A-frag for PV)
    float* Vs = sm + 3 * 64 * PQ;      // [s][dk]  64 x pitch 72 (B-frag for PV)

    const int qt  = blockIdx.x;
    const int bh  = blockIdx.y;
    const int tid = threadIdx.x;
    const int w   = tid >> 5;
    const int l   = tid & 31;
    const int lq = l >> 2, lr = l & 3;

    const float* Qg = g_Q + (size_t)bh * SEQ * DK + (size_t)qt * 64 * DK;
    const float* Kg = g_K + (size_t)bh * SEQ * DK;
    const float* Vg = g_V + (size_t)bh * SEQ * DK;

    const float scale = 0.125f;

    // stage Q (scaled, tf32)
    #pragma unroll
    for (int i = 0; i < 8; i++) {
        int idx = tid + i * 128;               // 1024 float4 slots
        int r = idx >> 4, c = (idx & 15) << 2;
        float4 v = *(const float4*)(Qg + (size_t)r * DK + c);
        v.x = to_tf32(v.x * scale); v.y = to_tf32(v.y * scale);
        v.z = to_tf32(v.z * scale); v.w = to_tf32(v.w * scale);
        *(float4*)&Qs[r * PQ + c] = v;
    }

    float m0 = -INFINITY, m1 = -INFINITY;
    float l0 = 0.f, l1 = 0.f;
    float o[8][4] = {};                        // 8 n8-tiles over dk

    for (int j = 0; j <= qt; j++) {
        // stage K (pitch 68) and V (pitch 72), tf32
        #pragma unroll
        for (int i = 0; i < 8; i++) {
            int idx = tid + i * 128;
            int r = idx >> 4, c = (idx & 15) << 2;
            float4 kv = *(const float4*)(Kg + (size_t)(j * 64 + r) * DK + c);
            kv.x = to_tf32(kv.x); kv.y = to_tf32(kv.y);
            kv.z = to_tf32(kv.z); kv.w = to_tf32(kv.w);
            *(float4*)&Ks[r * PQ + c] = kv;
            float4 vv = *(const float4*)(Vg + (size_t)(j * 64 + r) * DK + c);
            vv.x = to_tf32(vv.x); vv.y = to_tf32(vv.y);
            vv.z = to_tf32(vv.z); vv.w = to_tf32(vv.w);
            *(float4*)&Vs[r * PB + c] = vv;
        }
        __syncthreads();

        // S = Q K^T : warp rows [16w, 16w+16), all 64 cols
        float s[8][4] = {};
        #pragma unroll
        for (int kk = 0; kk < 8; kk++) {
            unsigned a[4], b[8][2];
            int abase = (w * 16 + lq) * PQ + kk * 8 + lr;
            a[0] = fu(Qs[abase]);
            a[1] = fu(Qs[abase + 8 * PQ]);
            a[2] = fu(Qs[abase + 4]);
            a[3] = fu(Qs[abase + 8 * PQ + 4]);
            #pragma unroll
            for (int ni = 0; ni < 8; ni++) {
                int bbase = (ni * 8 + lq) * PQ + kk * 8 + lr;  // B[k=dk][n=s] from Ks[s][dk]
                b[ni][0] = fu(Ks[bbase]);
                b[ni][1] = fu(Ks[bbase + 4]);
            }
            #pragma unroll
            for (int ni = 0; ni < 8; ni++)
                mma_tf32(s[ni], a, b[ni]);
        }

        // causal mask on diagonal tile
        if (j == qt) {
            int r1m = w * 16 + lq, r2m = r1m + 8;
            #pragma unroll
            for (int ni = 0; ni < 8; ni++) {
                int c0 = ni * 8 + 2 * lr;
                if (c0     > r1m) s[ni][0] = -INFINITY;
                if (c0 + 1 > r1m) s[ni][1] = -INFINITY;
                if (c0     > r2m) s[ni][2] = -INFINITY;
                if (c0 + 1 > r2m) s[ni][3] = -INFINITY;
            }
        }

        // online softmax: rows r1 (regs 0,1) and r2 (regs 2,3)
        float rm0 = -INFINITY, rm1 = -INFINITY;
        #pragma unroll
        for (int ni = 0; ni < 8; ni++) {
            rm0 = fmaxf(rm0, fmaxf(s[ni][0], s[ni][1]));
            rm1 = fmaxf(rm1, fmaxf(s[ni][2], s[ni][3]));
        }
        rm0 = fmaxf(rm0, __shfl_xor_sync(0xffffffffu, rm0, 1));
        rm0 = fmaxf(rm0, __shfl_xor_sync(0xffffffffu, rm0, 2));
        rm1 = fmaxf(rm1, __shfl_xor_sync(0xffffffffu, rm1, 1));
        rm1 = fmaxf(rm1, __shfl_xor_sync(0xffffffffu, rm1, 2));

        float mn0 = fmaxf(m0, rm0), mn1 = fmaxf(m1, rm1);
        float corr0 = __expf(m0 - mn0), corr1 = __expf(m1 - mn1);
        m0 = mn0; m1 = mn1;

        float rs0 = 0.f, rs1 = 0.f;
        const int r1 = w * 16 + lq, r2 = r1 + 8;
        #pragma unroll
        for (int ni = 0; ni < 8; ni++) {
            float p0 = __expf(s[ni][0] - mn0);
            float p1 = __expf(s[ni][1] - mn0);
            float p2 = __expf(s[ni][2] - mn1);
            float p3 = __expf(s[ni][3] - mn1);
            rs0 += p0 + p1; rs1 += p2 + p3;
            int c = ni * 8 + 2 * lr;
            *(float2*)&Ps[r1 * PQ + c] = make_float2(to_tf32(p0), to_tf32(p1));
            *(float2*)&Ps[r2 * PQ + c] = make_float2(to_tf32(p2), to_tf32(p3));
            o[ni][0] *= corr0; o[ni][1] *= corr0;
            o[ni][2] *= corr1; o[ni][3] *= corr1;
        }
        rs0 += __shfl_xor_sync(0xffffffffu, rs0, 1);
        rs0 += __shfl_xor_sync(0xffffffffu, rs0, 2);
        rs1 += __shfl_xor_sync(0xffffffffu, rs1, 1);
        rs1 += __shfl_xor_sync(0xffffffffu, rs1, 2);
        l0 = l0 * corr0 + rs0;
        l1 = l1 * corr1 + rs1;

        __syncwarp();   // Ps rows are warp-private; order stores before frag loads

        // O += P V : A = Ps rows [16w,16w+16); B = Vs[k=s][n=dk]
        #pragma unroll
        for (int kk = 0; kk < 8; kk++) {
            unsigned a[4], b[8][2];
            int abase = (w * 16 + lq) * PQ + kk * 8 + lr;
            a[0] = fu(Ps[abase]);
            a[1] = fu(Ps[abase + 8 * PQ]);
            a[2] = fu(Ps[abase + 4]);
            a[3] = fu(Ps[abase + 8 * PQ + 4]);
            #pragma unroll
            for (int ni = 0; ni < 8; ni++) {
                int bbase = (kk * 8 + lr) * PB + ni * 8 + lq;
                b[ni][0] = fu(Vs[bbase]);
                b[ni][1] = fu(Vs[bbase + 4 * PB]);
            }
            #pragma unroll
            for (int ni = 0; ni < 8; ni++)
                mma_tf32(o[ni], a, b[ni]);
        }
        __syncthreads();   // all warps done with Ks/Vs before next stage
    }

    // normalize + write ctx [B, S, H*DK]
    const int b_idx = bh / NH, h = bh % NH;
    const float inv0 = 1.0f / l0, inv1 = 1.0f / l1;
    const int r1 = w * 16 + lq, r2 = r1 + 8;
    float* c1 = g_C + (size_t)(b_idx * SEQ + qt * 64 + r1) * DMODEL + h * DK;
    float* c2 = g_C + (size_t)(b_idx * SEQ + qt * 64 + r2) * DMODEL + h * DK;
    #pragma unroll
    for (int ni = 0; ni < 8; ni++) {
        int c = ni * 8 + 2 * lr;
        *(float2*)(c1 + c) = make_float2(o[ni][0] * inv0, o[ni][1] * inv0);
        *(float2*)(c2 + c) = make_float2(o[ni][2] * inv1, o[ni][3] * inv1);
    }
}

// ---------------------------------------------------------------------------
// Output projection: out = ctx @ Wo + bo. grid (MROWS/128, DMODEL/64), block 256
// ---------------------------------------------------------------------------
__global__ void __launch_bounds__(256) out_proj(
    const float* __restrict__ Wo, const float* __restrict__ bo,
    float* __restrict__ out)
{
    __shared__ float As[128 * PA];
    __shared__ float Bs[32 * PB];

    const int mt = blockIdx.x, nt = blockIdx.y;
    const int tid = threadIdx.x;
    const int w  = tid >> 5;
    const int l  = tid & 31;
    const int lq = l >> 2, lr = l & 3;
    const int wm = w >> 1, wn = w & 1;
    const int row0 = mt * 128, n0 = nt * 64;

    float acc[2][4][4] = {};

    for (int k0 = 0; k0 < DMODEL; k0 += 32) {
        #pragma unroll
        for (int i = 0; i < 4; i++) {
            int idx = tid + i * 256;
            int r = idx >> 3, kk = (idx & 7) << 2;
            float4 v = *(const float4*)(g_C + (size_t)(row0 + r) * DMODEL + k0 + kk);
            v.x = to_tf32(v.x); v.y = to_tf32(v.y);
            v.z = to_tf32(v.z); v.w = to_tf32(v.w);
            *(float4*)&As[r * PA + kk] = v;
        }
        #pragma unroll
        for (int i = 0; i < 2; i++) {
            int idx = tid + i * 256;
            int kr = idx >> 4, nn = (idx & 15) << 2;
            float4 v = *(const float4*)(Wo + (size_t)(k0 + kr) * DMODEL + n0 + nn);
            v.x = to_tf32(v.x); v.y = to_tf32(v.y);
            v.z = to_tf32(v.z); v.w = to_tf32(v.w);
            *(float4*)&Bs[kr * PB + nn] = v;
        }
        __syncthreads();

        #pragma unroll
        for (int kk = 0; kk < 4; kk++) {
            unsigned a[2][4], b[4][2];
            #pragma unroll
            for (int mi = 0; mi < 2; mi++) {
                int base = (wm * 32 + mi * 16 + lq) * PA + kk * 8 + lr;
                a[mi][0] = fu(As[base]);
                a[mi][1] = fu(As[base + 8 * PA]);
                a[mi][2] = fu(As[base + 4]);
                a[mi][3] = fu(As[base + 8 * PA + 4]);
            }
            #pragma unroll
            for (int ni = 0; ni < 4; ni++) {
                int base = (kk * 8 + lr) * PB + wn * 32 + ni * 8 + lq;
                b[ni][0] = fu(Bs[base]);
                b[ni][1] = fu(Bs[base + 4 * PB]);
            }
            #pragma unroll
            for (int mi = 0; mi < 2; mi++)
                #pragma unroll
                for (int ni = 0; ni < 4; ni++)
                    mma_tf32(acc[mi][ni], a[mi], b[ni]);
        }
        __syncthreads();
    }

    #pragma unroll
    for (int mi = 0; mi < 2; mi++)
        #pragma unroll
        for (int rh = 0; rh < 2; rh++) {
            int m = row0 + wm * 32 + mi * 16 + lq + rh * 8;
            #pragma unroll
            for (int ni = 0; ni < 4; ni++) {
                int col = n0 + wn * 32 + ni * 8 + 2 * lr;
                float2 bv = *(const float2*)(bo + col);
                float2 v = make_float2(acc[mi][ni][rh * 2 + 0] + bv.x,
                                       acc[mi][ni][rh * 2 + 1] + bv.y);
                *(float2*)(out + (size_t)m * DMODEL + col) = v;
            }
        }
}

// ---------------------------------------------------------------------------
extern "C" void kernel_launch(void* const* d_in, const int* in_sizes, int n_in,
                              void* d_out, int out_size)
{
    const float* x  = (const float*)d_in[0];
    const float* Wq = (const float*)d_in[1];
    const float* bq = (const float*)d_in[2];
    const float* Wk = (const float*)d_in[3];
    const float* bk = (const float*)d_in[4];
    const float* Wv = (const float*)d_in[5];
    const float* bv = (const float*)d_in[6];
    const float* Wo = (const float*)d_in[7];
    const float* bo = (const float*)d_in[8];
    float* out = (float*)d_out;

    cudaFuncSetAttribute(attn_flash, cudaFuncAttributeMaxDynamicSharedMemorySize, ATTN_SMEM);

    qkv_proj<<<dim3(MROWS / 128, NH, 3), 256>>>(x, Wq, bq, Wk, bk, Wv, bv);
    attn_flash<<<dim3(SEQ / 64, BATCH * NH), 128, ATTN_SMEM>>>();
    out_proj<<<dim3(MROWS / 128, DMODEL / 64), 256>>>(Wo, bo, out);
}

// round 6
// speedup vs baseline: 5.8641x; 1.1163x over previous
#include <cuda_runtime.h>
#include <math.h>

#define BATCH 4
#define SEQ   2048
#define DMODEL 1024
#define NH    16
#define DK    64
#define MROWS (BATCH*SEQ)   // 8192

// Scratch — Q/K/V in [B,H,S,DK], ctx in [B,S,H*DK]
__device__ __align__(256) float g_Q[BATCH*NH*SEQ*DK];
__device__ __align__(256) float g_K[BATCH*NH*SEQ*DK];
__device__ __align__(256) float g_V[BATCH*NH*SEQ*DK];
__device__ __align__(256) float g_C[BATCH*SEQ*NH*DK];

// ---------------------------------------------------------------------------
// tf32 helpers
// ---------------------------------------------------------------------------
__device__ __forceinline__ float to_tf32(float x) {
    float y;
    asm("cvt.rna.tf32.f32 %0, %1;" : "=f"(y) : "f"(x));
    return y;
}

__device__ __forceinline__ void mma_tf32(float d[4], const unsigned a[4], const unsigned b[2]) {
    asm volatile(
        "mma.sync.aligned.m16n8k8.row.col.f32.tf32.tf32.f32 "
        "{%0,%1,%2,%3}, {%4,%5,%6,%7}, {%8,%9}, {%0,%1,%2,%3};"
        : "+f"(d[0]), "+f"(d[1]), "+f"(d[2]), "+f"(d[3])
        : "r"(a[0]), "r"(a[1]), "r"(a[2]), "r"(a[3]), "r"(b[0]), "r"(b[1]));
}

__device__ __forceinline__ unsigned fu(float x) { return __float_as_uint(x); }

// Fragment pitches (floats):
//  A-frag pattern (l>>2)*P + (l&3): conflict-free iff P % 32 == 4
//     width 32 -> 36;  width 64 -> 68
//  B-frag pattern (l&3)*P + (l>>2): conflict-free iff P % 32 == 8
//     width 64 -> 72;  width 128 -> 136
#define PA  36
#define PQ  68
#define PB  72
#define PBW 136

// ---------------------------------------------------------------------------
// Fused QKV projection as one GEMM: X[8192x1024] @ Wcat[1024x3072].
// Column mapping: n = mat*1024 + h*64 + dk. Tile 128x128, 8 warps (32x64 each).
// grid (MROWS/128, 3072/128) = (64, 24), block 256.
// ---------------------------------------------------------------------------
__global__ void __launch_bounds__(256) qkv_proj(
    const float* __restrict__ x,
    const float* __restrict__ Wq, const float* __restrict__ bq,
    const float* __restrict__ Wk, const float* __restrict__ bk,
    const float* __restrict__ Wv, const float* __restrict__ bv)
{
    __shared__ float As[128 * PA];    // 128 rows x 32 k   (pitch 36)
    __shared__ float Bs[32 * PBW];    // 32 k x 128 n      (pitch 136)

    const int row0 = blockIdx.x * 128;
    const int n0g  = blockIdx.y * 128;           // global fused column base
    const int mat  = n0g >> 10;                  // 0,1,2
    const int nm   = n0g & 1023;                 // column base within matrix
    const float* W; const float* bias; float* outp;
    if (mat == 0)      { W = Wq; bias = bq; outp = g_Q; }
    else if (mat == 1) { W = Wk; bias = bk; outp = g_K; }
    else               { W = Wv; bias = bv; outp = g_V; }

    const int tid = threadIdx.x;
    const int w  = tid >> 5;
    const int l  = tid & 31;
    const int lq = l >> 2, lr = l & 3;
    const int wm = w >> 1, wn = w & 1;           // warp grid 4 x 2, warp tile 32x64

    float acc[2][8][4] = {};

    for (int k0 = 0; k0 < DMODEL; k0 += 32) {
        // stage A: x[row0..row0+128) x k[k0..k0+32)
        #pragma unroll
        for (int i = 0; i < 4; i++) {
            int idx = tid + i * 256;             // 1024 float4 slots
            int r = idx >> 3, kk = (idx & 7) << 2;
            float4 v = *(const float4*)(x + (size_t)(row0 + r) * DMODEL + k0 + kk);
            v.x = to_tf32(v.x); v.y = to_tf32(v.y);
            v.z = to_tf32(v.z); v.w = to_tf32(v.w);
            *(float4*)&As[r * PA + kk] = v;
        }
        // stage B: W columns nm..nm+128 (2 heads), rows k0..k0+32
        // W[h][k][dk]: addr = h*DMODEL*DK + k*DK + dk
        #pragma unroll
        for (int i = 0; i < 4; i++) {
            int idx = tid + i * 256;             // 1024 float4 slots (32 x 32)
            int kr = idx >> 5, c4 = (idx & 31) << 2;
            int col = nm + c4;
            int h = col >> 6, dk = col & 63;
            float4 v = *(const float4*)(W + (size_t)h * DMODEL * DK
                                          + (size_t)(k0 + kr) * DK + dk);
            v.x = to_tf32(v.x); v.y = to_tf32(v.y);
            v.z = to_tf32(v.z); v.w = to_tf32(v.w);
            *(float4*)&Bs[kr * PBW + c4] = v;
        }
        __syncthreads();

        #pragma unroll
        for (int kk = 0; kk < 4; kk++) {
            unsigned a[2][4], b[8][2];
            #pragma unroll
            for (int mi = 0; mi < 2; mi++) {
                int base = (wm * 32 + mi * 16 + lq) * PA + kk * 8 + lr;
                a[mi][0] = fu(As[base]);
                a[mi][1] = fu(As[base + 8 * PA]);
                a[mi][2] = fu(As[base + 4]);
                a[mi][3] = fu(As[base + 8 * PA + 4]);
            }
            #pragma unroll
            for (int ni = 0; ni < 8; ni++) {
                int base = (kk * 8 + lr) * PBW + wn * 64 + ni * 8 + lq;
                b[ni][0] = fu(Bs[base]);
                b[ni][1] = fu(Bs[base + 4 * PBW]);
            }
            #pragma unroll
            for (int mi = 0; mi < 2; mi++)
                #pragma unroll
                for (int ni = 0; ni < 8; ni++)
                    mma_tf32(acc[mi][ni], a[mi], b[ni]);
        }
        __syncthreads();
    }

    // epilogue: bias + scatter into [B,H,S,DK]
    #pragma unroll
    for (int mi = 0; mi < 2; mi++)
        #pragma unroll
        for (int rh = 0; rh < 2; rh++) {
            int m = row0 + wm * 32 + mi * 16 + lq + rh * 8;
            int bi = m >> 11, s = m & (SEQ - 1);
            #pragma unroll
            for (int ni = 0; ni < 8; ni++) {
                int col = nm + wn * 64 + ni * 8 + 2 * lr;     // within-matrix col
                int h = col >> 6, dk = col & 63;
                float2 bv = *(const float2*)(bias + col);     // bias[h*64+dk] = bias[col]
                float2 v = make_float2(acc[mi][ni][rh * 2 + 0] + bv.x,
                                       acc[mi][ni][rh * 2 + 1] + bv.y);
                *(float2*)(outp + ((size_t)(bi * NH + h) * SEQ + s) * DK + dk) = v;
            }
        }
}

// ---------------------------------------------------------------------------
// Causal flash attention, tf32 MMA. q-tile 128, kv-tile 64.
// grid (SEQ/128, BATCH*NH) = (16, 64), block 256 (8 warps, 16 q-rows each).
// Dynamic smem.
// ---------------------------------------------------------------------------
#define ATTN_SMEM ((128 * PQ + 64 * PQ + 128 * PQ + 64 * PB) * 4)

__global__ void __launch_bounds__(256) attn_flash()
{
    extern __shared__ __align__(16) float sm[];
    float* Qs = sm;                          // [q][dk]  128 x pitch 68 (A-frag)
    float* Ks = sm + 128 * PQ;               // [s][dk]   64 x pitch 68 (B-frag for S)
    float* Ps = sm + 128 * PQ + 64 * PQ;     // [q][s]   128 x pitch 68 (A-frag for PV)
    float* Vs = sm + 256 * PQ + 64 * PQ;     // [s][dk]   64 x pitch 72 (B-frag for PV)

    const int qt  = blockIdx.x;
    const int bh  = blockIdx.y;
    const int tid = threadIdx.x;
    const int w   = tid >> 5;
    const int l   = tid & 31;
    const int lq = l >> 2, lr = l & 3;

    const float* Qg = g_Q + (size_t)bh * SEQ * DK + (size_t)qt * 128 * DK;
    const float* Kg = g_K + (size_t)bh * SEQ * DK;
    const float* Vg = g_V + (size_t)bh * SEQ * DK;

    const float scale = 0.125f;

    // stage Q (scaled, tf32): 128x64 = 2048 float4 / 256 thr = 8 iters
    #pragma unroll
    for (int i = 0; i < 8; i++) {
        int idx = tid + i * 256;
        int r = idx >> 4, c = (idx & 15) << 2;
        float4 v = *(const float4*)(Qg + (size_t)r * DK + c);
        v.x = to_tf32(v.x * scale); v.y = to_tf32(v.y * scale);
        v.z = to_tf32(v.z * scale); v.w = to_tf32(v.w * scale);
        *(float4*)&Qs[r * PQ + c] = v;
    }

    float m0 = -INFINITY, m1 = -INFINITY;
    float l0 = 0.f, l1 = 0.f;
    float o[8][4] = {};

    const int jmax = 2 * qt + 1;
    for (int j = 0; j <= jmax; j++) {
        // stage K (pitch 68) and V (pitch 72): 64x64 each, 4 iters
        #pragma unroll
        for (int i = 0; i < 4; i++) {
            int idx = tid + i * 256;
            int r = idx >> 4, c = (idx & 15) << 2;
            float4 kv = *(const float4*)(Kg + (size_t)(j * 64 + r) * DK + c);
            kv.x = to_tf32(kv.x); kv.y = to_tf32(kv.y);
            kv.z = to_tf32(kv.z); kv.w = to_tf32(kv.w);
            *(float4*)&Ks[r * PQ + c] = kv;
            float4 vv = *(const float4*)(Vg + (size_t)(j * 64 + r) * DK + c);
            vv.x = to_tf32(vv.x); vv.y = to_tf32(vv.y);
            vv.z = to_tf32(vv.z); vv.w = to_tf32(vv.w);
            *(float4*)&Vs[r * PB + c] = vv;
        }
        __syncthreads();

        // S = Q K^T : warp rows [16w, 16w+16), 64 cols
        float s[8][4] = {};
        #pragma unroll
        for (int kk = 0; kk < 8; kk++) {
            unsigned a[4], b[8][2];
            int abase = (w * 16 + lq) * PQ + kk * 8 + lr;
            a[0] = fu(Qs[abase]);
            a[1] = fu(Qs[abase + 8 * PQ]);
            a[2] = fu(Qs[abase + 4]);
            a[3] = fu(Qs[abase + 8 * PQ + 4]);
            #pragma unroll
            for (int ni = 0; ni < 8; ni++) {
                int bbase = (ni * 8 + lq) * PQ + kk * 8 + lr;
                b[ni][0] = fu(Ks[bbase]);
                b[ni][1] = fu(Ks[bbase + 4]);
            }
            #pragma unroll
            for (int ni = 0; ni < 8; ni++)
                mma_tf32(s[ni], a, b[ni]);
        }

        // causal mask: global col = 64j + c, global row = 128qt + r
        // mask iff c + 64*(j - 2qt) > r  (only possible when j >= 2qt)
        if (j >= 2 * qt) {
            int joff = (j - 2 * qt) << 6;      // 0 or 64
            int r1m = w * 16 + lq, r2m = r1m + 8;
            #pragma unroll
            for (int ni = 0; ni < 8; ni++) {
                int c0 = ni * 8 + 2 * lr + joff;
                if (c0     > r1m) s[ni][0] = -INFINITY;
                if (c0 + 1 > r1m) s[ni][1] = -INFINITY;
                if (c0     > r2m) s[ni][2] = -INFINITY;
                if (c0 + 1 > r2m) s[ni][3] = -INFINITY;
            }
        }

        // online softmax: rows r1 (regs 0,1) and r2 (regs 2,3)
        float rm0 = -INFINITY, rm1 = -INFINITY;
        #pragma unroll
        for (int ni = 0; ni < 8; ni++) {
            rm0 = fmaxf(rm0, fmaxf(s[ni][0], s[ni][1]));
            rm1 = fmaxf(rm1, fmaxf(s[ni][2], s[ni][3]));
        }
        rm0 = fmaxf(rm0, __shfl_xor_sync(0xffffffffu, rm0, 1));
        rm0 = fmaxf(rm0, __shfl_xor_sync(0xffffffffu, rm0, 2));
        rm1 = fmaxf(rm1, __shfl_xor_sync(0xffffffffu, rm1, 1));
        rm1 = fmaxf(rm1, __shfl_xor_sync(0xffffffffu, rm1, 2));

        float mn0 = fmaxf(m0, rm0), mn1 = fmaxf(m1, rm1);
        float corr0 = __expf(m0 - mn0), corr1 = __expf(m1 - mn1);
        m0 = mn0; m1 = mn1;

        float rs0 = 0.f, rs1 = 0.f;
        const int r1 = w * 16 + lq, r2 = r1 + 8;
        #pragma unroll
        for (int ni = 0; ni < 8; ni++) {
            float p0 = __expf(s[ni][0] - mn0);
            float p1 = __expf(s[ni][1] - mn0);
            float p2 = __expf(s[ni][2] - mn1);
            float p3 = __expf(s[ni][3] - mn1);
            rs0 += p0 + p1; rs1 += p2 + p3;
            int c = ni * 8 + 2 * lr;
            *(float2*)&Ps[r1 * PQ + c] = make_float2(to_tf32(p0), to_tf32(p1));
            *(float2*)&Ps[r2 * PQ + c] = make_float2(to_tf32(p2), to_tf32(p3));
            o[ni][0] *= corr0; o[ni][1] *= corr0;
            o[ni][2] *= corr1; o[ni][3] *= corr1;
        }
        rs0 += __shfl_xor_sync(0xffffffffu, rs0, 1);
        rs0 += __shfl_xor_sync(0xffffffffu, rs0, 2);
        rs1 += __shfl_xor_sync(0xffffffffu, rs1, 1);
        rs1 += __shfl_xor_sync(0xffffffffu, rs1, 2);
        l0 = l0 * corr0 + rs0;
        l1 = l1 * corr1 + rs1;

        __syncwarp();   // Ps rows are warp-private; order stores before frag loads

        // O += P V
        #pragma unroll
        for (int kk = 0; kk < 8; kk++) {
            unsigned a[4], b[8][2];
            int abase = (w * 16 + lq) * PQ + kk * 8 + lr;
            a[0] = fu(Ps[abase]);
            a[1] = fu(Ps[abase + 8 * PQ]);
            a[2] = fu(Ps[abase + 4]);
            a[3] = fu(Ps[abase + 8 * PQ + 4]);
            #pragma unroll
            for (int ni = 0; ni < 8; ni++) {
                int bbase = (kk * 8 + lr) * PB + ni * 8 + lq;
                b[ni][0] = fu(Vs[bbase]);
                b[ni][1] = fu(Vs[bbase + 4 * PB]);
            }
            #pragma unroll
            for (int ni = 0; ni < 8; ni++)
                mma_tf32(o[ni], a, b[ni]);
        }
        __syncthreads();
    }

    // normalize + write ctx [B, S, H*DK]
    const int b_idx = bh / NH, h = bh % NH;
    const float inv0 = 1.0f / l0, inv1 = 1.0f / l1;
    const int r1 = w * 16 + lq, r2 = r1 + 8;
    float* c1 = g_C + (size_t)(b_idx * SEQ + qt * 128 + r1) * DMODEL + h * DK;
    float* c2 = g_C + (size_t)(b_idx * SEQ + qt * 128 + r2) * DMODEL + h * DK;
    #pragma unroll
    for (int ni = 0; ni < 8; ni++) {
        int c = ni * 8 + 2 * lr;
        *(float2*)(c1 + c) = make_float2(o[ni][0] * inv0, o[ni][1] * inv0);
        *(float2*)(c2 + c) = make_float2(o[ni][2] * inv1, o[ni][3] * inv1);
    }
}

// ---------------------------------------------------------------------------
// Output projection: out = ctx @ Wo + bo. Tile 128x128, warp 32x64.
// grid (MROWS/128, DMODEL/128) = (64, 8), block 256.
// ---------------------------------------------------------------------------
__global__ void __launch_bounds__(256) out_proj(
    const float* __restrict__ Wo, const float* __restrict__ bo,
    float* __restrict__ out)
{
    __shared__ float As[128 * PA];
    __shared__ float Bs[32 * PBW];

    const int row0 = blockIdx.x * 128, n0 = blockIdx.y * 128;
    const int tid = threadIdx.x;
    const int w  = tid >> 5;
    const int l  = tid & 31;
    const int lq = l >> 2, lr = l & 3;
    const int wm = w >> 1, wn = w & 1;

    float acc[2][8][4] = {};

    for (int k0 = 0; k0 < DMODEL; k0 += 32) {
        #pragma unroll
        for (int i = 0; i < 4; i++) {
            int idx = tid + i * 256;
            int r = idx >> 3, kk = (idx & 7) << 2;
            float4 v = *(const float4*)(g_C + (size_t)(row0 + r) * DMODEL + k0 + kk);
            v.x = to_tf32(v.x); v.y = to_tf32(v.y);
            v.z = to_tf32(v.z); v.w = to_tf32(v.w);
            *(float4*)&As[r * PA + kk] = v;
        }
        #pragma unroll
        for (int i = 0; i < 4; i++) {
            int idx = tid + i * 256;
            int kr = idx >> 5, c4 = (idx & 31) << 2;
            float4 v = *(const float4*)(Wo + (size_t)(k0 + kr) * DMODEL + n0 + c4);
            v.x = to_tf32(v.x); v.y = to_tf32(v.y);
            v.z = to_tf32(v.z); v.w = to_tf32(v.w);
            *(float4*)&Bs[kr * PBW + c4] = v;
        }
        __syncthreads();

        #pragma unroll
        for (int kk = 0; kk < 4; kk++) {
            unsigned a[2][4], b[8][2];
            #pragma unroll
            for (int mi = 0; mi < 2; mi++) {
                int base = (wm * 32 + mi * 16 + lq) * PA + kk * 8 + lr;
                a[mi][0] = fu(As[base]);
                a[mi][1] = fu(As[base + 8 * PA]);
                a[mi][2] = fu(As[base + 4]);
                a[mi][3] = fu(As[base + 8 * PA + 4]);
            }
            #pragma unroll
            for (int ni = 0; ni < 8; ni++) {
                int base = (kk * 8 + lr) * PBW + wn * 64 + ni * 8 + lq;
                b[ni][0] = fu(Bs[base]);
                b[ni][1] = fu(Bs[base + 4 * PBW]);
            }
            #pragma unroll
            for (int mi = 0; mi < 2; mi++)
                #pragma unroll
                for (int ni = 0; ni < 8; ni++)
                    mma_tf32(acc[mi][ni], a[mi], b[ni]);
        }
        __syncthreads();
    }

    #pragma unroll
    for (int mi = 0; mi < 2; mi++)
        #pragma unroll
        for (int rh = 0; rh < 2; rh++) {
            int m = row0 + wm * 32 + mi * 16 + lq + rh * 8;
            #pragma unroll
            for (int ni = 0; ni < 8; ni++) {
                int col = n0 + wn * 64 + ni * 8 + 2 * lr;
                float2 bv = *(const float2*)(bo + col);
                float2 v = make_float2(acc[mi][ni][rh * 2 + 0] + bv.x,
                                       acc[mi][ni][rh * 2 + 1] + bv.y);
                *(float2*)(out + (size_t)m * DMODEL + col) = v;
            }
        }
}

// ---------------------------------------------------------------------------
extern "C" void kernel_launch(void* const* d_in, const int* in_sizes, int n_in,
                              void* d_out, int out_size)
{
    const float* x  = (const float*)d_in[0];
    const float* Wq = (const float*)d_in[1];
    const float* bq = (const float*)d_in[2];
    const float* Wk = (const float*)d_in[3];
    const float* bk = (const float*)d_in[4];
    const float* Wv = (const float*)d_in[5];
    const float* bv = (const float*)d_in[6];
    const float* Wo = (const float*)d_in[7];
    const float* bo = (const float*)d_in[8];
    float* out = (float*)d_out;

    cudaFuncSetAttribute(attn_flash, cudaFuncAttributeMaxDynamicSharedMemorySize, ATTN_SMEM);

    qkv_proj<<<dim3(MROWS / 128, 3 * DMODEL / 128), 256>>>(x, Wq, bq, Wk, bk, Wv, bv);
    attn_flash<<<dim3(SEQ / 128, BATCH * NH), 256, ATTN_SMEM>>>();
    out_proj<<<dim3(MROWS / 128, DMODEL / 128), 256>>>(Wo, bo, out);
}

// round 7
// speedup vs baseline: 6.0837x; 1.0374x over previous
#include <cuda_runtime.h>
#include <math.h>

#define BATCH 4
#define SEQ   2048
#define DMODEL 1024
#define NH    16
#define DK    64
#define MROWS (BATCH*SEQ)   // 8192

// Scratch — all tf32-prerounded except where noted
__device__ __align__(256) float g_Q[BATCH*NH*SEQ*DK];
__device__ __align__(256) float g_K[BATCH*NH*SEQ*DK];
__device__ __align__(256) float g_V[BATCH*NH*SEQ*DK];
__device__ __align__(256) float g_C[BATCH*SEQ*NH*DK];
__device__ __align__(256) float g_X [MROWS*DMODEL];        // tf32(x)
__device__ __align__(256) float g_Wq[NH*DMODEL*DK];
__device__ __align__(256) float g_Wk[NH*DMODEL*DK];
__device__ __align__(256) float g_Wv[NH*DMODEL*DK];
__device__ __align__(256) float g_Wo[DMODEL*DMODEL];

// ---------------------------------------------------------------------------
__device__ __forceinline__ float to_tf32(float x) {
    float y;
    asm("cvt.rna.tf32.f32 %0, %1;" : "=f"(y) : "f"(x));
    return y;
}

__device__ __forceinline__ void mma_tf32(float d[4], const unsigned a[4], const unsigned b[2]) {
    asm volatile(
        "mma.sync.aligned.m16n8k8.row.col.f32.tf32.tf32.f32 "
        "{%0,%1,%2,%3}, {%4,%5,%6,%7}, {%8,%9}, {%0,%1,%2,%3};"
        : "+f"(d[0]), "+f"(d[1]), "+f"(d[2]), "+f"(d[3])
        : "r"(a[0]), "r"(a[1]), "r"(a[2]), "r"(a[3]), "r"(b[0]), "r"(b[1]));
}

__device__ __forceinline__ unsigned fu(float x) { return __float_as_uint(x); }

__device__ __forceinline__ void cp16(float* smem, const float* gmem) {
    unsigned s = (unsigned)__cvta_generic_to_shared(smem);
    asm volatile("cp.async.cg.shared.global [%0], [%1], 16;" :: "r"(s), "l"(gmem));
}
#define CP_COMMIT()  asm volatile("cp.async.commit_group;")
#define CP_WAIT1()   asm volatile("cp.async.wait_group 1;")
#define CP_WAIT0()   asm volatile("cp.async.wait_group 0;")

// Fragment pitches (floats):
//  A-frag pattern (l>>2)*P + (l&3): conflict-free iff P % 32 == 4 -> 36 / 68
//  B-frag pattern (l&3)*P + (l>>2): conflict-free iff P % 32 == 8 -> 72 / 136
#define PA  36
#define PQ  68
#define PB  72
#define PBW 136

// ---------------------------------------------------------------------------
// tf32 pre-conversion (grid-strided float4)
// ---------------------------------------------------------------------------
__global__ void cvt_tf32(const float* __restrict__ src, float* __restrict__ dst, int n4)
{
    int i = blockIdx.x * blockDim.x + threadIdx.x;
    if (i < n4) {
        float4 v = ((const float4*)src)[i];
        v.x = to_tf32(v.x); v.y = to_tf32(v.y);
        v.z = to_tf32(v.z); v.w = to_tf32(v.w);
        ((float4*)dst)[i] = v;
    }
}

// ---------------------------------------------------------------------------
// Fused QKV projection GEMM: g_X[8192x1024] @ Wcat[1024x3072].
// Tile 128x128, 8 warps (32x64). 2-stage cp.async pipeline.
// grid (64, 24), block 256, dyn smem 71680 B.
// ---------------------------------------------------------------------------
#define GEMM_SMEM ((128*PA + 32*PBW) * 2 * 4)
#define STG (128*PA + 32*PBW)          // floats per stage

__global__ void __launch_bounds__(256, 2) qkv_proj(
    const float* __restrict__ bq, const float* __restrict__ bk,
    const float* __restrict__ bv)
{
    extern __shared__ __align__(16) float sm[];

    const int row0 = blockIdx.x * 128;
    const int n0g  = blockIdx.y * 128;
    const int mat  = n0g >> 10;
    const int nm   = n0g & 1023;
    const float* W; const float* bias; float* outp;
    if (mat == 0)      { W = g_Wq; bias = bq; outp = g_Q; }
    else if (mat == 1) { W = g_Wk; bias = bk; outp = g_K; }
    else               { W = g_Wv; bias = bv; outp = g_V; }

    const int tid = threadIdx.x;
    const int w  = tid >> 5;
    const int l  = tid & 31;
    const int lq = l >> 2, lr = l & 3;
    const int wm = w >> 1, wn = w & 1;

    float acc[2][8][4] = {};

    // stage loader: chunk c -> buffer s
    auto stage = [&](int c, int s) {
        float* As = sm + s * STG;
        float* Bs = As + 128 * PA;
        int k0 = c * 32;
        #pragma unroll
        for (int i = 0; i < 4; i++) {
            int idx = tid + i * 256;
            int r = idx >> 3, kk = (idx & 7) << 2;
            cp16(&As[r * PA + kk], g_X + (size_t)(row0 + r) * DMODEL + k0 + kk);
        }
        #pragma unroll
        for (int i = 0; i < 4; i++) {
            int idx = tid + i * 256;
            int kr = idx >> 5, c4 = (idx & 31) << 2;
            int col = nm + c4;
            int h = col >> 6, dk = col & 63;
            cp16(&Bs[kr * PBW + c4],
                 W + (size_t)h * DMODEL * DK + (size_t)(k0 + kr) * DK + dk);
        }
        CP_COMMIT();
    };

    stage(0, 0);

    for (int c = 0; c < 32; c++) {
        if (c + 1 < 32) { stage(c + 1, (c + 1) & 1); CP_WAIT1(); }
        else            { CP_WAIT0(); }
        __syncthreads();

        const float* As = sm + (c & 1) * STG;
        const float* Bs = As + 128 * PA;

        #pragma unroll
        for (int kk = 0; kk < 4; kk++) {
            unsigned a[2][4], b[8][2];
            #pragma unroll
            for (int mi = 0; mi < 2; mi++) {
                int base = (wm * 32 + mi * 16 + lq) * PA + kk * 8 + lr;
                a[mi][0] = fu(As[base]);
                a[mi][1] = fu(As[base + 8 * PA]);
                a[mi][2] = fu(As[base + 4]);
                a[mi][3] = fu(As[base + 8 * PA + 4]);
            }
            #pragma unroll
            for (int ni = 0; ni < 8; ni++) {
                int base = (kk * 8 + lr) * PBW + wn * 64 + ni * 8 + lq;
                b[ni][0] = fu(Bs[base]);
                b[ni][1] = fu(Bs[base + 4 * PBW]);
            }
            #pragma unroll
            for (int mi = 0; mi < 2; mi++)
                #pragma unroll
                for (int ni = 0; ni < 8; ni++)
                    mma_tf32(acc[mi][ni], a[mi], b[ni]);
        }
        __syncthreads();
    }

    // epilogue: +bias, pre-round to tf32, scatter [B,H,S,DK]
    #pragma unroll
    for (int mi = 0; mi < 2; mi++)
        #pragma unroll
        for (int rh = 0; rh < 2; rh++) {
            int m = row0 + wm * 32 + mi * 16 + lq + rh * 8;
            int bi = m >> 11, s = m & (SEQ - 1);
            #pragma unroll
            for (int ni = 0; ni < 8; ni++) {
                int col = nm + wn * 64 + ni * 8 + 2 * lr;
                int h = col >> 6, dk = col & 63;
                float2 bv = *(const float2*)(bias + col);
                float2 v = make_float2(to_tf32(acc[mi][ni][rh * 2 + 0] + bv.x),
                                       to_tf32(acc[mi][ni][rh * 2 + 1] + bv.y));
                *(float2*)(outp + ((size_t)(bi * NH + h) * SEQ + s) * DK + dk) = v;
            }
        }
}

// ---------------------------------------------------------------------------
// Causal flash attention. q-tile 128, kv-tile 64, 2-stage cp.async K/V.
// grid (16, 64), block 256 (8 warps x 16 q-rows). dyn smem 141312 B.
// ---------------------------------------------------------------------------
#define KVSTG (64*PQ + 64*PB)
#define ATTN_SMEM ((128*PQ + 128*PQ + 2*KVSTG) * 4)

__global__ void __launch_bounds__(256, 1) attn_flash()
{
    extern __shared__ __align__(16) float sm[];
    float* Qs  = sm;                        // [q][dk] 128 x 68
    float* Ps  = sm + 128 * PQ;             // [q][s]  128 x 68
    float* KV0 = sm + 256 * PQ;             // stage 0: Ks 64x68, Vs 64x72
    float* KV1 = KV0 + KVSTG;               // stage 1

    const int qt  = blockIdx.x;
    const int bh  = blockIdx.y;
    const int tid = threadIdx.x;
    const int w   = tid >> 5;
    const int l   = tid & 31;
    const int lq = l >> 2, lr = l & 3;

    const float* Qg = g_Q + (size_t)bh * SEQ * DK + (size_t)qt * 128 * DK;
    const float* Kg = g_K + (size_t)bh * SEQ * DK;
    const float* Vg = g_V + (size_t)bh * SEQ * DK;

    const int jmax = 2 * qt + 1;

    auto stage_kv = [&](int j, float* KV) {
        float* Ks = KV;
        float* Vs = KV + 64 * PQ;
        #pragma unroll
        for (int i = 0; i < 4; i++) {
            int idx = tid + i * 256;
            int r = idx >> 4, c = (idx & 15) << 2;
            cp16(&Ks[r * PQ + c], Kg + (size_t)(j * 64 + r) * DK + c);
            cp16(&Vs[r * PB + c], Vg + (size_t)(j * 64 + r) * DK + c);
        }
        CP_COMMIT();
    };

    stage_kv(0, KV0);

    // stage Q (g_Q already tf32; *0.125 is exact pow2 scale)
    #pragma unroll
    for (int i = 0; i < 8; i++) {
        int idx = tid + i * 256;
        int r = idx >> 4, c = (idx & 15) << 2;
        float4 v = *(const float4*)(Qg + (size_t)r * DK + c);
        v.x *= 0.125f; v.y *= 0.125f; v.z *= 0.125f; v.w *= 0.125f;
        *(float4*)&Qs[r * PQ + c] = v;
    }

    float m0 = -INFINITY, m1 = -INFINITY;
    float l0 = 0.f, l1 = 0.f;
    float o[8][4] = {};

    for (int j = 0; j <= jmax; j++) {
        if (j + 1 <= jmax) { stage_kv(j + 1, (j & 1) ? KV0 : KV1); CP_WAIT1(); }
        else               { CP_WAIT0(); }
        __syncthreads();

        const float* Ks = (j & 1) ? KV1 : KV0;
        const float* Vs = Ks + 64 * PQ;

        // S = Q K^T : warp rows [16w, 16w+16), 64 cols
        float s[8][4] = {};
        #pragma unroll
        for (int kk = 0; kk < 8; kk++) {
            unsigned a[4], b[8][2];
            int abase = (w * 16 + lq) * PQ + kk * 8 + lr;
            a[0] = fu(Qs[abase]);
            a[1] = fu(Qs[abase + 8 * PQ]);
            a[2] = fu(Qs[abase + 4]);
            a[3] = fu(Qs[abase + 8 * PQ + 4]);
            #pragma unroll
            for (int ni = 0; ni < 8; ni++) {
                int bbase = (ni * 8 + lq) * PQ + kk * 8 + lr;
                b[ni][0] = fu(Ks[bbase]);
                b[ni][1] = fu(Ks[bbase + 4]);
            }
            #pragma unroll
            for (int ni = 0; ni < 8; ni++)
                mma_tf32(s[ni], a, b[ni]);
        }

        // causal mask (global col = 64j + c, row = 128qt + r)
        if (j >= 2 * qt) {
            int joff = (j - 2 * qt) << 6;
            int r1m = w * 16 + lq, r2m = r1m + 8;
            #pragma unroll
            for (int ni = 0; ni < 8; ni++) {
                int c0 = ni * 8 + 2 * lr + joff;
                if (c0     > r1m) s[ni][0] = -INFINITY;
                if (c0 + 1 > r1m) s[ni][1] = -INFINITY;
                if (c0     > r2m) s[ni][2] = -INFINITY;
                if (c0 + 1 > r2m) s[ni][3] = -INFINITY;
            }
        }

        // online softmax
        float rm0 = -INFINITY, rm1 = -INFINITY;
        #pragma unroll
        for (int ni = 0; ni < 8; ni++) {
            rm0 = fmaxf(rm0, fmaxf(s[ni][0], s[ni][1]));
            rm1 = fmaxf(rm1, fmaxf(s[ni][2], s[ni][3]));
        }
        rm0 = fmaxf(rm0, __shfl_xor_sync(0xffffffffu, rm0, 1));
        rm0 = fmaxf(rm0, __shfl_xor_sync(0xffffffffu, rm0, 2));
        rm1 = fmaxf(rm1, __shfl_xor_sync(0xffffffffu, rm1, 1));
        rm1 = fmaxf(rm1, __shfl_xor_sync(0xffffffffu, rm1, 2));

        float mn0 = fmaxf(m0, rm0), mn1 = fmaxf(m1, rm1);
        float corr0 = __expf(m0 - mn0), corr1 = __expf(m1 - mn1);
        m0 = mn0; m1 = mn1;

        float rs0 = 0.f, rs1 = 0.f;
        const int r1 = w * 16 + lq, r2 = r1 + 8;
        #pragma unroll
        for (int ni = 0; ni < 8; ni++) {
            float p0 = __expf(s[ni][0] - mn0);
            float p1 = __expf(s[ni][1] - mn0);
            float p2 = __expf(s[ni][2] - mn1);
            float p3 = __expf(s[ni][3] - mn1);
            rs0 += p0 + p1; rs1 += p2 + p3;
            int c = ni * 8 + 2 * lr;
            *(float2*)&Ps[r1 * PQ + c] = make_float2(to_tf32(p0), to_tf32(p1));
            *(float2*)&Ps[r2 * PQ + c] = make_float2(to_tf32(p2), to_tf32(p3));
            o[ni][0] *= corr0; o[ni][1] *= corr0;
            o[ni][2] *= corr1; o[ni][3] *= corr1;
        }
        rs0 += __shfl_xor_sync(0xffffffffu, rs0, 1);
        rs0 += __shfl_xor_sync(0xffffffffu, rs0, 2);
        rs1 += __shfl_xor_sync(0xffffffffu, rs1, 1);
        rs1 += __shfl_xor_sync(0xffffffffu, rs1, 2);
        l0 = l0 * corr0 + rs0;
        l1 = l1 * corr1 + rs1;

        __syncwarp();   // Ps rows warp-private

        // O += P V
        #pragma unroll
        for (int kk = 0; kk < 8; kk++) {
            unsigned a[4], b[8][2];
            int abase = (w * 16 + lq) * PQ + kk * 8 + lr;
            a[0] = fu(Ps[abase]);
            a[1] = fu(Ps[abase + 8 * PQ]);
            a[2] = fu(Ps[abase + 4]);
            a[3] = fu(Ps[abase + 8 * PQ + 4]);
            #pragma unroll
            for (int ni = 0; ni < 8; ni++) {
                int bbase = (kk * 8 + lr) * PB + ni * 8 + lq;
                b[ni][0] = fu(Vs[bbase]);
                b[ni][1] = fu(Vs[bbase + 4 * PB]);
            }
            #pragma unroll
            for (int ni = 0; ni < 8; ni++)
                mma_tf32(o[ni], a, b[ni]);
        }
        __syncthreads();
    }

    // normalize + write ctx [B, S, H*DK], pre-rounded tf32 for out_proj
    const int b_idx = bh / NH, h = bh % NH;
    const float inv0 = 1.0f / l0, inv1 = 1.0f / l1;
    const int r1 = w * 16 + lq, r2 = r1 + 8;
    float* c1 = g_C + (size_t)(b_idx * SEQ + qt * 128 + r1) * DMODEL + h * DK;
    float* c2 = g_C + (size_t)(b_idx * SEQ + qt * 128 + r2) * DMODEL + h * DK;
    #pragma unroll
    for (int ni = 0; ni < 8; ni++) {
        int c = ni * 8 + 2 * lr;
        *(float2*)(c1 + c) = make_float2(to_tf32(o[ni][0] * inv0), to_tf32(o[ni][1] * inv0));
        *(float2*)(c2 + c) = make_float2(to_tf32(o[ni][2] * inv1), to_tf32(o[ni][3] * inv1));
    }
}

// ---------------------------------------------------------------------------
// Output projection: out = g_C @ g_Wo + bo. Tile 128x128, cp.async pipeline.
// grid (64, 8), block 256, dyn smem 71680 B.
// ---------------------------------------------------------------------------
__global__ void __launch_bounds__(256, 2) out_proj(
    const float* __restrict__ bo, float* __restrict__ out)
{
    extern __shared__ __align__(16) float sm[];

    const int row0 = blockIdx.x * 128, n0 = blockIdx.y * 128;
    const int tid = threadIdx.x;
    const int w  = tid >> 5;
    const int l  = tid & 31;
    const int lq = l >> 2, lr = l & 3;
    const int wm = w >> 1, wn = w & 1;

    float acc[2][8][4] = {};

    auto stage = [&](int c, int s) {
        float* As = sm + s * STG;
        float* Bs = As + 128 * PA;
        int k0 = c * 32;
        #pragma unroll
        for (int i = 0; i < 4; i++) {
            int idx = tid + i * 256;
            int r = idx >> 3, kk = (idx & 7) << 2;
            cp16(&As[r * PA + kk], g_C + (size_t)(row0 + r) * DMODEL + k0 + kk);
        }
        #pragma unroll
        for (int i = 0; i < 4; i++) {
            int idx = tid + i * 256;
            int kr = idx >> 5, c4 = (idx & 31) << 2;
            cp16(&Bs[kr * PBW + c4], g_Wo + (size_t)(k0 + kr) * DMODEL + n0 + c4);
        }
        CP_COMMIT();
    };

    stage(0, 0);

    for (int c = 0; c < 32; c++) {
        if (c + 1 < 32) { stage(c + 1, (c + 1) & 1); CP_WAIT1(); }
        else            { CP_WAIT0(); }
        __syncthreads();

        const float* As = sm + (c & 1) * STG;
        const float* Bs = As + 128 * PA;

        #pragma unroll
        for (int kk = 0; kk < 4; kk++) {
            unsigned a[2][4], b[8][2];
            #pragma unroll
            for (int mi = 0; mi < 2; mi++) {
                int base = (wm * 32 + mi * 16 + lq) * PA + kk * 8 + lr;
                a[mi][0] = fu(As[base]);
                a[mi][1] = fu(As[base + 8 * PA]);
                a[mi][2] = fu(As[base + 4]);
                a[mi][3] = fu(As[base + 8 * PA + 4]);
            }
            #pragma unroll
            for (int ni = 0; ni < 8; ni++) {
                int base = (kk * 8 + lr) * PBW + wn * 64 + ni * 8 + lq;
                b[ni][0] = fu(Bs[base]);
                b[ni][1] = fu(Bs[base + 4 * PBW]);
            }
            #pragma unroll
            for (int mi = 0; mi < 2; mi++)
                #pragma unroll
                for (int ni = 0; ni < 8; ni++)
                    mma_tf32(acc[mi][ni], a[mi], b[ni]);
        }
        __syncthreads();
    }

    #pragma unroll
    for (int mi = 0; mi < 2; mi++)
        #pragma unroll
        for (int rh = 0; rh < 2; rh++) {
            int m = row0 + wm * 32 + mi * 16 + lq + rh * 8;
            #pragma unroll
            for (int ni = 0; ni < 8; ni++) {
                int col = n0 + wn * 64 + ni * 8 + 2 * lr;
                float2 bv = *(const float2*)(bo + col);
                float2 v = make_float2(acc[mi][ni][rh * 2 + 0] + bv.x,
                                       acc[mi][ni][rh * 2 + 1] + bv.y);
                *(float2*)(out + (size_t)m * DMODEL + col) = v;
            }
        }
}

// ---------------------------------------------------------------------------
extern "C" void kernel_launch(void* const* d_in, const int* in_sizes, int n_in,
                              void* d_out, int out_size)
{
    const float* x  = (const float*)d_in[0];
    const float* Wq = (const float*)d_in[1];
    const float* bq = (const float*)d_in[2];
    const float* Wk = (const float*)d_in[3];
    const float* bk = (const float*)d_in[4];
    const float* Wv = (const float*)d_in[5];
    const float* bv = (const float*)d_in[6];
    const float* Wo = (const float*)d_in[7];
    const float* bo = (const float*)d_in[8];
    float* out = (float*)d_out;

    cudaFuncSetAttribute(qkv_proj,  cudaFuncAttributeMaxDynamicSharedMemorySize, GEMM_SMEM);
    cudaFuncSetAttribute(attn_flash, cudaFuncAttributeMaxDynamicSharedMemorySize, ATTN_SMEM);
    cudaFuncSetAttribute(out_proj,  cudaFuncAttributeMaxDynamicSharedMemorySize, GEMM_SMEM);

    // tf32 pre-conversion
    float *gx, *gwq, *gwk, *gwv, *gwo;
    cudaGetSymbolAddress((void**)&gx,  g_X);
    cudaGetSymbolAddress((void**)&gwq, g_Wq);
    cudaGetSymbolAddress((void**)&gwk, g_Wk);
    cudaGetSymbolAddress((void**)&gwv, g_Wv);
    cudaGetSymbolAddress((void**)&gwo, g_Wo);
    const int NX = MROWS * DMODEL / 4;          // 2,097,152
    const int NW = NH * DMODEL * DK / 4;        // 262,144
    const int NO = DMODEL * DMODEL / 4;         // 262,144
    cvt_tf32<<<(NX + 255) / 256, 256>>>(x,  gx,  NX);
    cvt_tf32<<<(NW + 255) / 256, 256>>>(Wq, gwq, NW);
    cvt_tf32<<<(NW + 255) / 256, 256>>>(Wk, gwk, NW);
    cvt_tf32<<<(NW + 255) / 256, 256>>>(Wv, gwv, NW);
    cvt_tf32<<<(NO + 255) / 256, 256>>>(Wo, gwo, NO);

    qkv_proj<<<dim3(MROWS / 128, 3 * DMODEL / 128), 256, GEMM_SMEM>>>(bq, bk, bv);
    attn_flash<<<dim3(SEQ / 128, BATCH * NH), 256, ATTN_SMEM>>>();
    out_proj<<<dim3(MROWS / 128, DMODEL / 128), 256, GEMM_SMEM>>>(bo, out);
}

// round 10
// speedup vs baseline: 9.7763x; 1.6070x over previous
#include <cuda_runtime.h>
#include <cuda_fp16.h>
#include <math.h>
#include <stdint.h>

#define BATCH 4
#define SEQ   2048
#define DMODEL 1024
#define NH    16
#define DK    64
#define MROWS (BATCH*SEQ)   // 8192

// Scratch (halves unless noted)
__device__ __align__(256) __half g_Qh [BATCH*NH*SEQ*DK];   // [bh][s][dk], pre-scaled by 1/8
__device__ __align__(256) __half g_Kh [BATCH*NH*SEQ*DK];   // [bh][s][dk]
__device__ __align__(256) __half g_Vth[BATCH*NH*SEQ*DK];   // [bh][dk][s]  (transposed!)
__device__ __align__(256) __half g_Ch [MROWS*DMODEL];      // ctx [m][n]
__device__ __align__(256) __half g_Xh [MROWS*DMODEL];      // x  [m][k]
__device__ __align__(256) __half g_WqT[DMODEL*DMODEL];     // [n][k]
__device__ __align__(256) __half g_WkT[DMODEL*DMODEL];
__device__ __align__(256) __half g_WvT[DMODEL*DMODEL];
__device__ __align__(256) __half g_WoT[DMODEL*DMODEL];

// ---------------------------------------------------------------------------
__device__ __forceinline__ void mma_f16(float d[4], const unsigned a[4], const unsigned b[2]) {
    asm volatile(
        "mma.sync.aligned.m16n8k16.row.col.f32.f16.f16.f32 "
        "{%0,%1,%2,%3}, {%4,%5,%6,%7}, {%8,%9}, {%0,%1,%2,%3};"
        : "+f"(d[0]), "+f"(d[1]), "+f"(d[2]), "+f"(d[3])
        : "r"(a[0]), "r"(a[1]), "r"(a[2]), "r"(a[3]), "r"(b[0]), "r"(b[1]));
}
__device__ __forceinline__ unsigned hu(const __half* p) { return *(const unsigned*)p; }

__device__ __forceinline__ void cp16(void* smem, const void* gmem) {
    unsigned s = (unsigned)__cvta_generic_to_shared(smem);
    asm volatile("cp.async.cg.shared.global [%0], [%1], 16;" :: "r"(s), "l"(gmem));
}
#define CP_COMMIT()  asm volatile("cp.async.commit_group;")
#define CP_WAIT1()   asm volatile("cp.async.wait_group 1;")
#define CP_WAIT0()   asm volatile("cp.async.wait_group 0;")

// Pitches in halves. 32-bit LDS lanes hit words (row*Pw + lr): conflict-free
// iff Pw (words) == 4*odd mod 32.  width 32h -> 40h (20w); width 64h -> 72h (36w).
#define PW 40
#define PH 72

// ---------------------------------------------------------------------------
// Prep kernels
// ---------------------------------------------------------------------------
__global__ void cvt_x_h(const float* __restrict__ src, __half* __restrict__ dst, int n4)
{
    int i = blockIdx.x * blockDim.x + threadIdx.x;
    if (i < n4) {
        float4 v = ((const float4*)src)[i];
        ((__half2*)dst)[2*i]   = __floats2half2_rn(v.x, v.y);
        ((__half2*)dst)[2*i+1] = __floats2half2_rn(v.z, v.w);
    }
}
// W[h][k][dk] -> WT[n=h*64+dk][k]
__global__ void transpose_wqkv_h(const float* __restrict__ src, __half* __restrict__ dst)
{
    int i = blockIdx.x * blockDim.x + threadIdx.x;
    int n = i >> 10, k = i & 1023;
    int h = n >> 6, dk = n & 63;
    dst[i] = __float2half_rn(src[h * 65536 + k * 64 + dk]);
}
// Wo[k][n] -> WT[n][k]
__global__ void transpose_wo_h(const float* __restrict__ src, __half* __restrict__ dst)
{
    int i = blockIdx.x * blockDim.x + threadIdx.x;
    int n = i >> 10, k = i & 1023;
    dst[i] = __float2half_rn(src[k * 1024 + n]);
}

// ---------------------------------------------------------------------------
// Fused QKV GEMM: g_Xh[8192x1024] @ WT^T, tile 128x128, warp 32x64.
// fp16 mma m16n8k16, k-chunk 32 halves, 2-stage cp.async.
// grid (64, 24), block 256. dyn smem 40960 B.
// ---------------------------------------------------------------------------
#define STGH (128*PW + 128*PW)                  // halves per stage (A+B)
#define GEMM_SMEM (2 * STGH * 2)                // bytes

__global__ void __launch_bounds__(256, 2) qkv_proj(
    const float* __restrict__ bq, const float* __restrict__ bk,
    const float* __restrict__ bv)
{
    extern __shared__ __align__(16) __half smh[];

    const int row0 = blockIdx.x * 128;
    const int n0g  = blockIdx.y * 128;
    const int mat  = n0g >> 10;
    const int nm   = n0g & 1023;
    const __half* WT; const float* bias;
    if (mat == 0)      { WT = g_WqT; bias = bq; }
    else if (mat == 1) { WT = g_WkT; bias = bk; }
    else               { WT = g_WvT; bias = bv; }

    const int tid = threadIdx.x;
    const int w  = tid >> 5;
    const int l  = tid & 31;
    const int lq = l >> 2, lr = l & 3;
    const int wm = w >> 1, wn = w & 1;          // warp grid 4x2, warp tile 32x64

    float acc[2][8][4] = {};

    auto stage = [&](int c, int s) {
        __half* As = smh + s * STGH;
        __half* Bs = As + 128 * PW;
        int k0 = c * 32;
        #pragma unroll
        for (int i = 0; i < 2; i++) {           // A: 512 16B segs (128 rows x 4)
            int idx = tid + i * 256;
            int r = idx >> 2, j = idx & 3;
            cp16(&As[r * PW + j * 8], g_Xh + (size_t)(row0 + r) * DMODEL + k0 + j * 8);
        }
        #pragma unroll
        for (int i = 0; i < 2; i++) {           // B: 512 segs
            int idx = tid + i * 256;
            int rn = idx >> 2, j = idx & 3;
            cp16(&Bs[rn * PW + j * 8], WT + (size_t)(nm + rn) * DMODEL + k0 + j * 8);
        }
        CP_COMMIT();
    };

    stage(0, 0);

    for (int c = 0; c < 32; c++) {
        if (c + 1 < 32) { stage(c + 1, (c + 1) & 1); CP_WAIT1(); }
        else            { CP_WAIT0(); }
        __syncthreads();

        const __half* As = smh + (c & 1) * STGH;
        const __half* Bs = As + 128 * PW;

        #pragma unroll
        for (int kk = 0; kk < 2; kk++) {        // 2 k16 steps per 32-chunk
            unsigned a[2][4], b[8][2];
            #pragma unroll
            for (int mi = 0; mi < 2; mi++) {
                int base = (wm * 32 + mi * 16 + lq) * PW + kk * 16 + 2 * lr;
                a[mi][0] = hu(&As[base]);
                a[mi][1] = hu(&As[base + 8 * PW]);
                a[mi][2] = hu(&As[base + 8]);
                a[mi][3] = hu(&As[base + 8 * PW + 8]);
            }
            #pragma unroll
            for (int ni = 0; ni < 8; ni++) {
                int base = (wn * 64 + ni * 8 + lq) * PW + kk * 16 + 2 * lr;
                b[ni][0] = hu(&Bs[base]);
                b[ni][1] = hu(&Bs[base + 8]);
            }
            #pragma unroll
            for (int mi = 0; mi < 2; mi++)
                #pragma unroll
                for (int ni = 0; ni < 8; ni++)
                    mma_f16(acc[mi][ni], a[mi], b[ni]);
        }
        __syncthreads();
    }

    // epilogue: +bias; Q pre-scaled; V transposed
    #pragma unroll
    for (int mi = 0; mi < 2; mi++)
        #pragma unroll
        for (int rh = 0; rh < 2; rh++) {
            int m = row0 + wm * 32 + mi * 16 + lq + rh * 8;
            int bi = m >> 11, s = m & (SEQ - 1);
            #pragma unroll
            for (int ni = 0; ni < 8; ni++) {
                int col = nm + wn * 64 + ni * 8 + 2 * lr;
                int h = col >> 6, dk = col & 63;
                float2 bv2 = *(const float2*)(bias + col);
                float v0 = acc[mi][ni][rh * 2 + 0] + bv2.x;
                float v1 = acc[mi][ni][rh * 2 + 1] + bv2.y;
                size_t bh = (size_t)(bi * NH + h);
                if (mat == 0) {
                    *(__half2*)(g_Qh + (bh * SEQ + s) * DK + dk) =
                        __floats2half2_rn(v0 * 0.125f, v1 * 0.125f);
                } else if (mat == 1) {
                    *(__half2*)(g_Kh + (bh * SEQ + s) * DK + dk) =
                        __floats2half2_rn(v0, v1);
                } else {
                    g_Vth[(bh * DK + dk)     * SEQ + s] = __float2half_rn(v0);
                    g_Vth[(bh * DK + dk + 1) * SEQ + s] = __float2half_rn(v1);
                }
            }
        }
}

// ---------------------------------------------------------------------------
// Causal flash attention fp16. q-tile 128, kv-tile 64, 2-stage cp.async.
// grid (16, 64), block 256 (8 warps x 16 q-rows). dyn smem 73728 B.
// ---------------------------------------------------------------------------
#define KVSTGH (64*PH + 64*PH)
#define ATTN_SMEM ((128*PH + 128*PH + 2*KVSTGH) * 2)

__global__ void __launch_bounds__(256, 2) attn_flash()
{
    extern __shared__ __align__(16) __half smh[];
    __half* Qs  = smh;                     // [q][dk] 128 x 72
    __half* Ps  = smh + 128 * PH;          // [q][s]  128 x 72
    __half* KV0 = smh + 256 * PH;          // stage0: Ks[s][dk] 64x72, Vt[dk][s] 64x72
    __half* KV1 = KV0 + KVSTGH;

    const int qt  = blockIdx.x;
    const int bh  = blockIdx.y;
    const int tid = threadIdx.x;
    const int w   = tid >> 5;
    const int l   = tid & 31;
    const int lq = l >> 2, lr = l & 3;

    const __half* Qg  = g_Qh  + (size_t)bh * SEQ * DK + (size_t)qt * 128 * DK;
    const __half* Kg  = g_Kh  + (size_t)bh * SEQ * DK;
    const __half* Vtg = g_Vth + (size_t)bh * DK * SEQ;

    const int jmax = 2 * qt + 1;

    auto stage_kv = [&](int j, __half* KV) {
        __half* Ks = KV;
        __half* Vt = KV + 64 * PH;
        #pragma unroll
        for (int i = 0; i < 2; i++) {          // K: 512 segs (64 rows x 8)
            int idx = tid + i * 256;
            int r = idx >> 3, j2 = idx & 7;
            cp16(&Ks[r * PH + j2 * 8], Kg + (size_t)(j * 64 + r) * DK + j2 * 8);
        }
        #pragma unroll
        for (int i = 0; i < 2; i++) {          // Vt rows = dk, cols = s-chunk
            int idx = tid + i * 256;
            int r = idx >> 3, j2 = idx & 7;
            cp16(&Vt[r * PH + j2 * 8], Vtg + (size_t)r * SEQ + j * 64 + j2 * 8);
        }
        CP_COMMIT();
    };

    // FIX (R9 NaN): stage Q FIRST as its own committed group, so the loop's
    // CP_WAIT1 (which leaves only the newest group in flight) guarantees
    // Q + KV0 have landed before the first MMA reads them.
    #pragma unroll
    for (int i = 0; i < 4; i++) {
        int idx = tid + i * 256;               // 1024 segs (128 rows x 8)
        int r = idx >> 3, j2 = idx & 7;
        cp16(&Qs[r * PH + j2 * 8], Qg + (size_t)r * DK + j2 * 8);
    }
    CP_COMMIT();

    stage_kv(0, KV0);

    float m0 = -INFINITY, m1 = -INFINITY;
    float l0 = 0.f, l1 = 0.f;
    float o[8][4] = {};

    for (int j = 0; j <= jmax; j++) {
        if (j + 1 <= jmax) { stage_kv(j + 1, (j & 1) ? KV0 : KV1); CP_WAIT1(); }
        else               { CP_WAIT0(); }
        __syncthreads();

        const __half* Ks = (j & 1) ? KV1 : KV0;
        const __half* Vt = Ks + 64 * PH;

        // S = Q K^T : warp rows [16w,16w+16), 64 cols, k=dk in 4 k16 steps
        float s[8][4] = {};
        #pragma unroll
        for (int kk = 0; kk < 4; kk++) {
            unsigned a[4], b[8][2];
            int abase = (w * 16 + lq) * PH + kk * 16 + 2 * lr;
            a[0] = hu(&Qs[abase]);
            a[1] = hu(&Qs[abase + 8 * PH]);
            a[2] = hu(&Qs[abase + 8]);
            a[3] = hu(&Qs[abase + 8 * PH + 8]);
            #pragma unroll
            for (int ni = 0; ni < 8; ni++) {
                int bbase = (ni * 8 + lq) * PH + kk * 16 + 2 * lr;
                b[ni][0] = hu(&Ks[bbase]);
                b[ni][1] = hu(&Ks[bbase + 8]);
            }
            #pragma unroll
            for (int ni = 0; ni < 8; ni++)
                mma_f16(s[ni], a, b[ni]);
        }

        // causal mask (global col = 64j + c, row = 128qt + r)
        if (j >= 2 * qt) {
            int joff = (j - 2 * qt) << 6;
            int r1m = w * 16 + lq, r2m = r1m + 8;
            #pragma unroll
            for (int ni = 0; ni < 8; ni++) {
                int c0 = ni * 8 + 2 * lr + joff;
                if (c0     > r1m) s[ni][0] = -INFINITY;
                if (c0 + 1 > r1m) s[ni][1] = -INFINITY;
                if (c0     > r2m) s[ni][2] = -INFINITY;
                if (c0 + 1 > r2m) s[ni][3] = -INFINITY;
            }
        }

        // online softmax (fp32)
        float rm0 = -INFINITY, rm1 = -INFINITY;
        #pragma unroll
        for (int ni = 0; ni < 8; ni++) {
            rm0 = fmaxf(rm0, fmaxf(s[ni][0], s[ni][1]));
            rm1 = fmaxf(rm1, fmaxf(s[ni][2], s[ni][3]));
        }
        rm0 = fmaxf(rm0, __shfl_xor_sync(0xffffffffu, rm0, 1));
        rm0 = fmaxf(rm0, __shfl_xor_sync(0xffffffffu, rm0, 2));
        rm1 = fmaxf(rm1, __shfl_xor_sync(0xffffffffu, rm1, 1));
        rm1 = fmaxf(rm1, __shfl_xor_sync(0xffffffffu, rm1, 2));

        float mn0 = fmaxf(m0, rm0), mn1 = fmaxf(m1, rm1);
        float corr0 = __expf(m0 - mn0), corr1 = __expf(m1 - mn1);
        m0 = mn0; m1 = mn1;

        float rs0 = 0.f, rs1 = 0.f;
        const int r1 = w * 16 + lq, r2 = r1 + 8;
        #pragma unroll
        for (int ni = 0; ni < 8; ni++) {
            float p0 = __expf(s[ni][0] - mn0);
            float p1 = __expf(s[ni][1] - mn0);
            float p2 = __expf(s[ni][2] - mn1);
            float p3 = __expf(s[ni][3] - mn1);
            rs0 += p0 + p1; rs1 += p2 + p3;
            int c = ni * 8 + 2 * lr;
            *(__half2*)&Ps[r1 * PH + c] = __floats2half2_rn(p0, p1);
            *(__half2*)&Ps[r2 * PH + c] = __floats2half2_rn(p2, p3);
            o[ni][0] *= corr0; o[ni][1] *= corr0;
            o[ni][2] *= corr1; o[ni][3] *= corr1;
        }
        rs0 += __shfl_xor_sync(0xffffffffu, rs0, 1);
        rs0 += __shfl_xor_sync(0xffffffffu, rs0, 2);
        rs1 += __shfl_xor_sync(0xffffffffu, rs1, 1);
        rs1 += __shfl_xor_sync(0xffffffffu, rs1, 2);
        l0 = l0 * corr0 + rs0;
        l1 = l1 * corr1 + rs1;

        __syncwarp();   // Ps rows warp-private: order stores before frag loads

        // O += P V : A = Ps [q][s], B[k=s][n=dk] = Vt[n=dk][k=s]
        #pragma unroll
        for (int kk = 0; kk < 4; kk++) {
            unsigned a[4], b[8][2];
            int abase = (w * 16 + lq) * PH + kk * 16 + 2 * lr;
            a[0] = hu(&Ps[abase]);
            a[1] = hu(&Ps[abase + 8 * PH]);
            a[2] = hu(&Ps[abase + 8]);
            a[3] = hu(&Ps[abase + 8 * PH + 8]);
            #pragma unroll
            for (int ni = 0; ni < 8; ni++) {
                int bbase = (ni * 8 + lq) * PH + kk * 16 + 2 * lr;
                b[ni][0] = hu(&Vt[bbase]);
                b[ni][1] = hu(&Vt[bbase + 8]);
            }
            #pragma unroll
            for (int ni = 0; ni < 8; ni++)
                mma_f16(o[ni], a, b[ni]);
        }
        __syncthreads();
    }

    // normalize + write ctx [B, S, H*DK] as half
    const int b_idx = bh / NH, h = bh % NH;
    const float inv0 = 1.0f / l0, inv1 = 1.0f / l1;
    const int r1 = w * 16 + lq, r2 = r1 + 8;
    __half* c1 = g_Ch + (size_t)(b_idx * SEQ + qt * 128 + r1) * DMODEL + h * DK;
    __half* c2 = g_Ch + (size_t)(b_idx * SEQ + qt * 128 + r2) * DMODEL + h * DK;
    #pragma unroll
    for (int ni = 0; ni < 8; ni++) {
        int c = ni * 8 + 2 * lr;
        *(__half2*)(c1 + c) = __floats2half2_rn(o[ni][0] * inv0, o[ni][1] * inv0);
        *(__half2*)(c2 + c) = __floats2half2_rn(o[ni][2] * inv1, o[ni][3] * inv1);
    }
}

// ---------------------------------------------------------------------------
// Output projection: out = g_Ch @ g_WoT^T + bo. Tile 128x128, fp16 mma.
// grid (64, 8), block 256. dyn smem 40960 B.
// ---------------------------------------------------------------------------
__global__ void __launch_bounds__(256, 2) out_proj(
    const float* __restrict__ bo, float* __restrict__ out)
{
    extern __shared__ __align__(16) __half smh[];

    const int row0 = blockIdx.x * 128, n0 = blockIdx.y * 128;
    const int tid = threadIdx.x;
    const int w  = tid >> 5;
    const int l  = tid & 31;
    const int lq = l >> 2, lr = l & 3;
    const int wm = w >> 1, wn = w & 1;

    float acc[2][8][4] = {};

    auto stage = [&](int c, int s) {
        __half* As = smh + s * STGH;
        __half* Bs = As + 128 * PW;
        int k0 = c * 32;
        #pragma unroll
        for (int i = 0; i < 2; i++) {
            int idx = tid + i * 256;
            int r = idx >> 2, j = idx & 3;
            cp16(&As[r * PW + j * 8], g_Ch + (size_t)(row0 + r) * DMODEL + k0 + j * 8);
        }
        #pragma unroll
        for (int i = 0; i < 2; i++) {
            int idx = tid + i * 256;
            int rn = idx >> 2, j = idx & 3;
            cp16(&Bs[rn * PW + j * 8], g_WoT + (size_t)(n0 + rn) * DMODEL + k0 + j * 8);
        }
        CP_COMMIT();
    };

    stage(0, 0);

    for (int c = 0; c < 32; c++) {
        if (c + 1 < 32) { stage(c + 1, (c + 1) & 1); CP_WAIT1(); }
        else            { CP_WAIT0(); }
        __syncthreads();

        const __half* As = smh + (c & 1) * STGH;
        const __half* Bs = As + 128 * PW;

        #pragma unroll
        for (int kk = 0; kk < 2; kk++) {
            unsigned a[2][4], b[8][2];
            #pragma unroll
            for (int mi = 0; mi < 2; mi++) {
                int base = (wm * 32 + mi * 16 + lq) * PW + kk * 16 + 2 * lr;
                a[mi][0] = hu(&As[base]);
                a[mi][1] = hu(&As[base + 8 * PW]);
                a[mi][2] = hu(&As[base + 8]);
                a[mi][3] = hu(&As[base + 8 * PW + 8]);
            }
            #pragma unroll
            for (int ni = 0; ni < 8; ni++) {
                int base = (wn * 64 + ni * 8 + lq) * PW + kk * 16 + 2 * lr;
                b[ni][0] = hu(&Bs[base]);
                b[ni][1] = hu(&Bs[base + 8]);
            }
            #pragma unroll
            for (int mi = 0; mi < 2; mi++)
                #pragma unroll
                for (int ni = 0; ni < 8; ni++)
                    mma_f16(acc[mi][ni], a[mi], b[ni]);
        }
        __syncthreads();
    }

    #pragma unroll
    for (int mi = 0; mi < 2; mi++)
        #pragma unroll
        for (int rh = 0; rh < 2; rh++) {
            int m = row0 + wm * 32 + mi * 16 + lq + rh * 8;
            #pragma unroll
            for (int ni = 0; ni < 8; ni++) {
                int col = n0 + wn * 64 + ni * 8 + 2 * lr;
                float2 bv2 = *(const float2*)(bo + col);
                float2 v = make_float2(acc[mi][ni][rh * 2 + 0] + bv2.x,
                                       acc[mi][ni][rh * 2 + 1] + bv2.y);
                *(float2*)(out + (size_t)m * DMODEL + col) = v;
            }
        }
}

// ---------------------------------------------------------------------------
extern "C" void kernel_launch(void* const* d_in, const int* in_sizes, int n_in,
                              void* d_out, int out_size)
{
    const float* x  = (const float*)d_in[0];
    const float* Wq = (const float*)d_in[1];
    const float* bq = (const float*)d_in[2];
    const float* Wk = (const float*)d_in[3];
    const float* bk = (const float*)d_in[4];
    const float* Wv = (const float*)d_in[5];
    const float* bv = (const float*)d_in[6];
    const float* Wo = (const float*)d_in[7];
    const float* bo = (const float*)d_in[8];
    float* out = (float*)d_out;

    cudaFuncSetAttribute(qkv_proj,   cudaFuncAttributeMaxDynamicSharedMemorySize, GEMM_SMEM);
    cudaFuncSetAttribute(attn_flash, cudaFuncAttributeMaxDynamicSharedMemorySize, ATTN_SMEM);
    cudaFuncSetAttribute(out_proj,   cudaFuncAttributeMaxDynamicSharedMemorySize, GEMM_SMEM);

    __half *gx, *gwq, *gwk, *gwv, *gwo;
    cudaGetSymbolAddress((void**)&gx,  g_Xh);
    cudaGetSymbolAddress((void**)&gwq, g_WqT);
    cudaGetSymbolAddress((void**)&gwk, g_WkT);
    cudaGetSymbolAddress((void**)&gwv, g_WvT);
    cudaGetSymbolAddress((void**)&gwo, g_WoT);

    const int NX4 = MROWS * DMODEL / 4;              // 2,097,152
    cvt_x_h<<<(NX4 + 255) / 256, 256>>>(x, gx, NX4);
    const int NT = DMODEL * DMODEL;                  // 1,048,576
    transpose_wqkv_h<<<NT / 256, 256>>>(Wq, gwq);
    transpose_wqkv_h<<<NT / 256, 256>>>(Wk, gwk);
    transpose_wqkv_h<<<NT / 256, 256>>>(Wv, gwv);
    transpose_wo_h  <<<NT / 256, 256>>>(Wo, gwo);

    qkv_proj<<<dim3(MROWS / 128, 24), 256, GEMM_SMEM>>>(bq, bk, bv);
    attn_flash<<<dim3(SEQ / 128, BATCH * NH), 256, ATTN_SMEM>>>();
    out_proj<<<dim3(MROWS / 128, 8), 256, GEMM_SMEM>>>(bo, out);
}

// round 12
// speedup vs baseline: 11.0887x; 1.1342x over previous
#include <cuda_runtime.h>
#include <cuda_fp16.h>
#include <math.h>
#include <stdint.h>

#define BATCH 4
#define SEQ   2048
#define DMODEL 1024
#define NH    16
#define DK    64
#define MROWS (BATCH*SEQ)   // 8192

// Scratch (halves unless noted)
__device__ __align__(256) __half g_Qh [BATCH*NH*SEQ*DK];   // [bh][s][dk], pre-scaled by 1/8
__device__ __align__(256) __half g_Kh [BATCH*NH*SEQ*DK];   // [bh][s][dk]
__device__ __align__(256) __half g_Vth[BATCH*NH*SEQ*DK];   // [bh][dk][s]  (transposed!)
__device__ __align__(256) __half g_Ch [MROWS*DMODEL];      // ctx [m][n]
__device__ __align__(256) __half g_Xh [MROWS*DMODEL];      // x  [m][k]
__device__ __align__(256) __half g_WqT[DMODEL*DMODEL];     // [n][k]
__device__ __align__(256) __half g_WkT[DMODEL*DMODEL];
__device__ __align__(256) __half g_WvT[DMODEL*DMODEL];
__device__ __align__(256) __half g_WoT[DMODEL*DMODEL];

// ---------------------------------------------------------------------------
__device__ __forceinline__ void mma_f16(float d[4], const unsigned a[4], const unsigned b[2]) {
    asm volatile(
        "mma.sync.aligned.m16n8k16.row.col.f32.f16.f16.f32 "
        "{%0,%1,%2,%3}, {%4,%5,%6,%7}, {%8,%9}, {%0,%1,%2,%3};"
        : "+f"(d[0]), "+f"(d[1]), "+f"(d[2]), "+f"(d[3])
        : "r"(a[0]), "r"(a[1]), "r"(a[2]), "r"(a[3]), "r"(b[0]), "r"(b[1]));
}
__device__ __forceinline__ void ldm_x4(unsigned& r0, unsigned& r1, unsigned& r2, unsigned& r3,
                                       const __half* p) {
    uint32_t addr = (uint32_t)__cvta_generic_to_shared(p);
    asm volatile("ldmatrix.sync.aligned.m8n8.x4.shared.b16 {%0,%1,%2,%3}, [%4];"
                 : "=r"(r0), "=r"(r1), "=r"(r2), "=r"(r3) : "r"(addr));
}

__device__ __forceinline__ void cp16(void* smem, const void* gmem) {
    unsigned s = (unsigned)__cvta_generic_to_shared(smem);
    asm volatile("cp.async.cg.shared.global [%0], [%1], 16;" :: "r"(s), "l"(gmem));
}
#define CP_COMMIT()  asm volatile("cp.async.commit_group;")
#define CP_WAIT1()   asm volatile("cp.async.wait_group 1;")
#define CP_WAIT0()   asm volatile("cp.async.wait_group 0;")

// Pitches in halves. ldmatrix conflict-free: PW=40h (20 words) and PH=72h (36
// words) spread 8 successive 16B row-chunks across all 32 banks; rows are
// 16B-aligned (80B / 144B pitches).
#define PW 40
#define PH 72

// ---------------------------------------------------------------------------
// Prep kernels
// ---------------------------------------------------------------------------
__global__ void cvt_x_h(const float* __restrict__ src, __half* __restrict__ dst, int n4)
{
    int i = blockIdx.x * blockDim.x + threadIdx.x;
    if (i < n4) {
        float4 v = ((const float4*)src)[i];
        ((__half2*)dst)[2*i]   = __floats2half2_rn(v.x, v.y);
        ((__half2*)dst)[2*i+1] = __floats2half2_rn(v.z, v.w);
    }
}

// W[h][k][dk] -> WT[n=h*64+dk][k], tiled smem transpose, all 3 matrices.
// grid (32 k-tiles, 2 dk-tiles, 48 = mat*16+h), block (32, 8).
__global__ void transpose_wqkv_t(const float* __restrict__ Wq,
                                 const float* __restrict__ Wk,
                                 const float* __restrict__ Wv)
{
    __shared__ __half tile[32][33];
    const int mat = blockIdx.z >> 4;
    const int h   = blockIdx.z & 15;
    const float* src = (mat == 0) ? Wq : (mat == 1) ? Wk : Wv;
    __half* dst      = (mat == 0) ? g_WqT : (mat == 1) ? g_WkT : g_WvT;
    const int k0 = blockIdx.x * 32, d0 = blockIdx.y * 32;
    const int tx = threadIdx.x, ty = threadIdx.y;
    #pragma unroll
    for (int i = 0; i < 4; i++) {
        int kk = ty + i * 8;
        tile[tx][kk] = __float2half_rn(src[h * 65536 + (k0 + kk) * 64 + d0 + tx]);
    }
    __syncthreads();
    #pragma unroll
    for (int i = 0; i < 4; i++) {
        int dd = ty + i * 8;
        dst[(size_t)(h * 64 + d0 + dd) * 1024 + k0 + tx] = tile[dd][tx];
    }
}

// Wo[k][n] -> WT[n][k], tiled. grid (32, 32), block (32, 8).
__global__ void transpose_wo_t(const float* __restrict__ src)
{
    __shared__ __half tile[32][33];
    const int k0 = blockIdx.x * 32, n0 = blockIdx.y * 32;
    const int tx = threadIdx.x, ty = threadIdx.y;
    #pragma unroll
    for (int i = 0; i < 4; i++) {
        int kk = ty + i * 8;
        tile[tx][kk] = __float2half_rn(src[(size_t)(k0 + kk) * 1024 + n0 + tx]);
    }
    __syncthreads();
    #pragma unroll
    for (int i = 0; i < 4; i++) {
        int dd = ty + i * 8;
        g_WoT[(size_t)(n0 + dd) * 1024 + k0 + tx] = tile[dd][tx];
    }
}

// ---------------------------------------------------------------------------
// Fused QKV GEMM: g_Xh[8192x1024] @ WT^T, tile 128x128, warp 32x64.
// fp16 mma m16n8k16 + ldmatrix, k-chunk 32, 2-stage cp.async.
// grid (64, 24), block 256. dyn smem 40960 B.
// ---------------------------------------------------------------------------
#define STGH (128*PW + 128*PW)
#define GEMM_SMEM (2 * STGH * 2)

__global__ void __launch_bounds__(256, 2) qkv_proj(
    const float* __restrict__ bq, const float* __restrict__ bk,
    const float* __restrict__ bv)
{
    extern __shared__ __align__(16) __half smh[];

    const int row0 = blockIdx.x * 128;
    const int n0g  = blockIdx.y * 128;
    const int mat  = n0g >> 10;
    const int nm   = n0g & 1023;
    const __half* WT; const float* bias;
    if (mat == 0)      { WT = g_WqT; bias = bq; }
    else if (mat == 1) { WT = g_WkT; bias = bk; }
    else               { WT = g_WvT; bias = bv; }

    const int tid = threadIdx.x;
    const int w  = tid >> 5;
    const int l  = tid & 31;
    const int lr = l & 3;
    const int wm = w >> 1, wn = w & 1;          // warp grid 4x2, warp tile 32x64

    // ldmatrix lane maps
    const int a_row = l & 15;                   // A/mat row within 16
    const int a_ko  = (l >> 4) << 3;            // A k offset (0/8)
    const int b_nr  = (l & 7) + ((l >> 4) << 3);// B n row within 16
    const int b_ko  = ((l >> 3) & 1) << 3;      // B k offset (0/8)

    float acc[2][8][4] = {};

    auto stage = [&](int c, int s) {
        __half* As = smh + s * STGH;
        __half* Bs = As + 128 * PW;
        int k0 = c * 32;
        #pragma unroll
        for (int i = 0; i < 2; i++) {
            int idx = tid + i * 256;
            int r = idx >> 2, j = idx & 3;
            cp16(&As[r * PW + j * 8], g_Xh + (size_t)(row0 + r) * DMODEL + k0 + j * 8);
        }
        #pragma unroll
        for (int i = 0; i < 2; i++) {
            int idx = tid + i * 256;
            int rn = idx >> 2, j = idx & 3;
            cp16(&Bs[rn * PW + j * 8], WT + (size_t)(nm + rn) * DMODEL + k0 + j * 8);
        }
        CP_COMMIT();
    };

    stage(0, 0);

    for (int c = 0; c < 32; c++) {
        if (c + 1 < 32) { stage(c + 1, (c + 1) & 1); CP_WAIT1(); }
        else            { CP_WAIT0(); }
        __syncthreads();

        const __half* As = smh + (c & 1) * STGH;
        const __half* Bs = As + 128 * PW;

        #pragma unroll
        for (int kk = 0; kk < 2; kk++) {
            unsigned a[2][4], b[8][2];
            #pragma unroll
            for (int mi = 0; mi < 2; mi++)
                ldm_x4(a[mi][0], a[mi][1], a[mi][2], a[mi][3],
                       &As[(wm * 32 + mi * 16 + a_row) * PW + kk * 16 + a_ko]);
            #pragma unroll
            for (int nj = 0; nj < 4; nj++)
                ldm_x4(b[2*nj][0], b[2*nj][1], b[2*nj+1][0], b[2*nj+1][1],
                       &Bs[(wn * 64 + nj * 16 + b_nr) * PW + kk * 16 + b_ko]);
            #pragma unroll
            for (int mi = 0; mi < 2; mi++)
                #pragma unroll
                for (int ni = 0; ni < 8; ni++)
                    mma_f16(acc[mi][ni], a[mi], b[ni]);
        }
        __syncthreads();
    }

    // epilogue: +bias; Q pre-scaled; V transposed
    const int lq = l >> 2;
    #pragma unroll
    for (int mi = 0; mi < 2; mi++)
        #pragma unroll
        for (int rh = 0; rh < 2; rh++) {
            int m = row0 + wm * 32 + mi * 16 + lq + rh * 8;
            int bi = m >> 11, s = m & (SEQ - 1);
            #pragma unroll
            for (int ni = 0; ni < 8; ni++) {
                int col = nm + wn * 64 + ni * 8 + 2 * lr;
                int h = col >> 6, dk = col & 63;
                float2 bv2 = *(const float2*)(bias + col);
                float v0 = acc[mi][ni][rh * 2 + 0] + bv2.x;
                float v1 = acc[mi][ni][rh * 2 + 1] + bv2.y;
                size_t bh = (size_t)(bi * NH + h);
                if (mat == 0) {
                    *(__half2*)(g_Qh + (bh * SEQ + s) * DK + dk) =
                        __floats2half2_rn(v0 * 0.125f, v1 * 0.125f);
                } else if (mat == 1) {
                    *(__half2*)(g_Kh + (bh * SEQ + s) * DK + dk) =
                        __floats2half2_rn(v0, v1);
                } else {
                    g_Vth[(bh * DK + dk)     * SEQ + s] = __float2half_rn(v0);
                    g_Vth[(bh * DK + dk + 1) * SEQ + s] = __float2half_rn(v1);
                }
            }
        }
}

// ---------------------------------------------------------------------------
// Causal flash attention fp16 + ldmatrix. q-tile 128, kv-tile 64.
// grid (16, 64), block 256 (8 warps x 16 q-rows). dyn smem 73728 B.
// ---------------------------------------------------------------------------
#define KVSTGH (64*PH + 64*PH)
#define ATTN_SMEM ((128*PH + 128*PH + 2*KVSTGH) * 2)

__global__ void __launch_bounds__(256, 2) attn_flash()
{
    extern __shared__ __align__(16) __half smh[];
    __half* Qs  = smh;                     // [q][dk] 128 x 72
    __half* Ps  = smh + 128 * PH;          // [q][s]  128 x 72
    __half* KV0 = smh + 256 * PH;          // stage0: Ks[s][dk] 64x72, Vt[dk][s] 64x72
    __half* KV1 = KV0 + KVSTGH;

    const int qt  = blockIdx.x;
    const int bh  = blockIdx.y;
    const int tid = threadIdx.x;
    const int w   = tid >> 5;
    const int l   = tid & 31;
    const int lq = l >> 2, lr = l & 3;

    const int a_row = l & 15;
    const int a_ko  = (l >> 4) << 3;
    const int b_nr  = (l & 7) + ((l >> 4) << 3);
    const int b_ko  = ((l >> 3) & 1) << 3;

    const __half* Qg  = g_Qh  + (size_t)bh * SEQ * DK + (size_t)qt * 128 * DK;
    const __half* Kg  = g_Kh  + (size_t)bh * SEQ * DK;
    const __half* Vtg = g_Vth + (size_t)bh * DK * SEQ;

    const int jmax = 2 * qt + 1;

    auto stage_kv = [&](int j, __half* KV) {
        __half* Ks = KV;
        __half* Vt = KV + 64 * PH;
        #pragma unroll
        for (int i = 0; i < 2; i++) {
            int idx = tid + i * 256;
            int r = idx >> 3, j2 = idx & 7;
            cp16(&Ks[r * PH + j2 * 8], Kg + (size_t)(j * 64 + r) * DK + j2 * 8);
        }
        #pragma unroll
        for (int i = 0; i < 2; i++) {
            int idx = tid + i * 256;
            int r = idx >> 3, j2 = idx & 7;
            cp16(&Vt[r * PH + j2 * 8], Vtg + (size_t)r * SEQ + j * 64 + j2 * 8);
        }
        CP_COMMIT();
    };

    // Q staged FIRST as its own committed (oldest) group — R9 fix.
    #pragma unroll
    for (int i = 0; i < 4; i++) {
        int idx = tid + i * 256;
        int r = idx >> 3, j2 = idx & 7;
        cp16(&Qs[r * PH + j2 * 8], Qg + (size_t)r * DK + j2 * 8);
    }
    CP_COMMIT();

    stage_kv(0, KV0);

    float m0 = -INFINITY, m1 = -INFINITY;
    float l0 = 0.f, l1 = 0.f;
    float o[8][4] = {};

    for (int j = 0; j <= jmax; j++) {
        if (j + 1 <= jmax) { stage_kv(j + 1, (j & 1) ? KV0 : KV1); CP_WAIT1(); }
        else               { CP_WAIT0(); }
        __syncthreads();

        const __half* Ks = (j & 1) ? KV1 : KV0;
        const __half* Vt = Ks + 64 * PH;

        // S = Q K^T : warp rows [16w,16w+16), 64 cols, 4 k16 steps
        float s[8][4] = {};
        #pragma unroll
        for (int kk = 0; kk < 4; kk++) {
            unsigned a[4], b[8][2];
            ldm_x4(a[0], a[1], a[2], a[3],
                   &Qs[(w * 16 + a_row) * PH + kk * 16 + a_ko]);
            #pragma unroll
            for (int nj = 0; nj < 4; nj++)
                ldm_x4(b[2*nj][0], b[2*nj][1], b[2*nj+1][0], b[2*nj+1][1],
                       &Ks[(nj * 16 + b_nr) * PH + kk * 16 + b_ko]);
            #pragma unroll
            for (int ni = 0; ni < 8; ni++)
                mma_f16(s[ni], a, b[ni]);
        }

        // causal mask (global col = 64j + c, row = 128qt + r)
        if (j >= 2 * qt) {
            int joff = (j - 2 * qt) << 6;
            int r1m = w * 16 + lq, r2m = r1m + 8;
            #pragma unroll
            for (int ni = 0; ni < 8; ni++) {
                int c0 = ni * 8 + 2 * lr + joff;
                if (c0     > r1m) s[ni][0] = -INFINITY;
                if (c0 + 1 > r1m) s[ni][1] = -INFINITY;
                if (c0     > r2m) s[ni][2] = -INFINITY;
                if (c0 + 1 > r2m) s[ni][3] = -INFINITY;
            }
        }

        // online softmax (fp32)
        float rm0 = -INFINITY, rm1 = -INFINITY;
        #pragma unroll
        for (int ni = 0; ni < 8; ni++) {
            rm0 = fmaxf(rm0, fmaxf(s[ni][0], s[ni][1]));
            rm1 = fmaxf(rm1, fmaxf(s[ni][2], s[ni][3]));
        }
        rm0 = fmaxf(rm0, __shfl_xor_sync(0xffffffffu, rm0, 1));
        rm0 = fmaxf(rm0, __shfl_xor_sync(0xffffffffu, rm0, 2));
        rm1 = fmaxf(rm1, __shfl_xor_sync(0xffffffffu, rm1, 1));
        rm1 = fmaxf(rm1, __shfl_xor_sync(0xffffffffu, rm1, 2));

        float mn0 = fmaxf(m0, rm0), mn1 = fmaxf(m1, rm1);
        float corr0 = __expf(m0 - mn0), corr1 = __expf(m1 - mn1);
        m0 = mn0; m1 = mn1;

        float rs0 = 0.f, rs1 = 0.f;
        const int r1 = w * 16 + lq, r2 = r1 + 8;
        #pragma unroll
        for (int ni = 0; ni < 8; ni++) {
            float p0 = __expf(s[ni][0] - mn0);
            float p1 = __expf(s[ni][1] - mn0);
            float p2 = __expf(s[ni][2] - mn1);
            float p3 = __expf(s[ni][3] - mn1);
            rs0 += p0 + p1; rs1 += p2 + p3;
            int c = ni * 8 + 2 * lr;
            *(__half2*)&Ps[r1 * PH + c] = __floats2half2_rn(p0, p1);
            *(__half2*)&Ps[r2 * PH + c] = __floats2half2_rn(p2, p3);
            o[ni][0] *= corr0; o[ni][1] *= corr0;
            o[ni][2] *= corr1; o[ni][3] *= corr1;
        }
        rs0 += __shfl_xor_sync(0xffffffffu, rs0, 1);
        rs0 += __shfl_xor_sync(0xffffffffu, rs0, 2);
        rs1 += __shfl_xor_sync(0xffffffffu, rs1, 1);
        rs1 += __shfl_xor_sync(0xffffffffu, rs1, 2);
        l0 = l0 * corr0 + rs0;
        l1 = l1 * corr1 + rs1;

        __syncwarp();   // Ps rows warp-private: order stores before ldmatrix

        // O += P V : A = Ps [q][s], B[k=s][n=dk] = Vt[n=dk][k=s]
        #pragma unroll
        for (int kk = 0; kk < 4; kk++) {
            unsigned a[4], b[8][2];
            ldm_x4(a[0], a[1], a[2], a[3],
                   &Ps[(w * 16 + a_row) * PH + kk * 16 + a_ko]);
            #pragma unroll
            for (int nj = 0; nj < 4; nj++)
                ldm_x4(b[2*nj][0], b[2*nj][1], b[2*nj+1][0], b[2*nj+1][1],
                       &Vt[(nj * 16 + b_nr) * PH + kk * 16 + b_ko]);
            #pragma unroll
            for (int ni = 0; ni < 8; ni++)
                mma_f16(o[ni], a, b[ni]);
        }
        __syncthreads();
    }

    // normalize + write ctx [B, S, H*DK] as half
    const int b_idx = bh / NH, h = bh % NH;
    const float inv0 = 1.0f / l0, inv1 = 1.0f / l1;
    const int r1 = w * 16 + lq, r2 = r1 + 8;
    __half* c1 = g_Ch + (size_t)(b_idx * SEQ + qt * 128 + r1) * DMODEL + h * DK;
    __half* c2 = g_Ch + (size_t)(b_idx * SEQ + qt * 128 + r2) * DMODEL + h * DK;
    #pragma unroll
    for (int ni = 0; ni < 8; ni++) {
        int c = ni * 8 + 2 * lr;
        *(__half2*)(c1 + c) = __floats2half2_rn(o[ni][0] * inv0, o[ni][1] * inv0);
        *(__half2*)(c2 + c) = __floats2half2_rn(o[ni][2] * inv1, o[ni][3] * inv1);
    }
}

// ---------------------------------------------------------------------------
// Output projection: out = g_Ch @ g_WoT^T + bo. Tile 128x128, fp16 + ldmatrix.
// grid (64, 8), block 256. dyn smem 40960 B.
// ---------------------------------------------------------------------------
__global__ void __launch_bounds__(256, 2) out_proj(
    const float* __restrict__ bo, float* __restrict__ out)
{
    extern __shared__ __align__(16) __half smh[];

    const int row0 = blockIdx.x * 128, n0 = blockIdx.y * 128;
    const int tid = threadIdx.x;
    const int w  = tid >> 5;
    const int l  = tid & 31;
    const int lr = l & 3;
    const int wm = w >> 1, wn = w & 1;

    const int a_row = l & 15;
    const int a_ko  = (l >> 4) << 3;
    const int b_nr  = (l & 7) + ((l >> 4) << 3);
    const int b_ko  = ((l >> 3) & 1) << 3;

    float acc[2][8][4] = {};

    auto stage = [&](int c, int s) {
        __half* As = smh + s * STGH;
        __half* Bs = As + 128 * PW;
        int k0 = c * 32;
        #pragma unroll
        for (int i = 0; i < 2; i++) {
            int idx = tid + i * 256;
            int r = idx >> 2, j = idx & 3;
            cp16(&As[r * PW + j * 8], g_Ch + (size_t)(row0 + r) * DMODEL + k0 + j * 8);
        }
        #pragma unroll
        for (int i = 0; i < 2; i++) {
            int idx = tid + i * 256;
            int rn = idx >> 2, j = idx & 3;
            cp16(&Bs[rn * PW + j * 8], g_WoT + (size_t)(n0 + rn) * DMODEL + k0 + j * 8);
        }
        CP_COMMIT();
    };

    stage(0, 0);

    for (int c = 0; c < 32; c++) {
        if (c + 1 < 32) { stage(c + 1, (c + 1) & 1); CP_WAIT1(); }
        else            { CP_WAIT0(); }
        __syncthreads();

        const __half* As = smh + (c & 1) * STGH;
        const __half* Bs = As + 128 * PW;

        #pragma unroll
        for (int kk = 0; kk < 2; kk++) {
            unsigned a[2][4], b[8][2];
            #pragma unroll
            for (int mi = 0; mi < 2; mi++)
                ldm_x4(a[mi][0], a[mi][1], a[mi][2], a[mi][3],
                       &As[(wm * 32 + mi * 16 + a_row) * PW + kk * 16 + a_ko]);
            #pragma unroll
            for (int nj = 0; nj < 4; nj++)
                ldm_x4(b[2*nj][0], b[2*nj][1], b[2*nj+1][0], b[2*nj+1][1],
                       &Bs[(wn * 64 + nj * 16 + b_nr) * PW + kk * 16 + b_ko]);
            #pragma unroll
            for (int mi = 0; mi < 2; mi++)
                #pragma unroll
                for (int ni = 0; ni < 8; ni++)
                    mma_f16(acc[mi][ni], a[mi], b[ni]);
        }
        __syncthreads();
    }

    const int lq = l >> 2;
    #pragma unroll
    for (int mi = 0; mi < 2; mi++)
        #pragma unroll
        for (int rh = 0; rh < 2; rh++) {
            int m = row0 + wm * 32 + mi * 16 + lq + rh * 8;
            #pragma unroll
            for (int ni = 0; ni < 8; ni++) {
                int col = n0 + wn * 64 + ni * 8 + 2 * lr;
                float2 bv2 = *(const float2*)(bo + col);
                float2 v = make_float2(acc[mi][ni][rh * 2 + 0] + bv2.x,
                                       acc[mi][ni][rh * 2 + 1] + bv2.y);
                *(float2*)(out + (size_t)m * DMODEL + col) = v;
            }
        }
}

// ---------------------------------------------------------------------------
extern "C" void kernel_launch(void* const* d_in, const int* in_sizes, int n_in,
                              void* d_out, int out_size)
{
    const float* x  = (const float*)d_in[0];
    const float* Wq = (const float*)d_in[1];
    const float* bq = (const float*)d_in[2];
    const float* Wk = (const float*)d_in[3];
    const float* bk = (const float*)d_in[4];
    const float* Wv = (const float*)d_in[5];
    const float* bv = (const float*)d_in[6];
    const float* Wo = (const float*)d_in[7];
    const float* bo = (const float*)d_in[8];
    float* out = (float*)d_out;

    cudaFuncSetAttribute(qkv_proj,   cudaFuncAttributeMaxDynamicSharedMemorySize, GEMM_SMEM);
    cudaFuncSetAttribute(attn_flash, cudaFuncAttributeMaxDynamicSharedMemorySize, ATTN_SMEM);
    cudaFuncSetAttribute(out_proj,   cudaFuncAttributeMaxDynamicSharedMemorySize, GEMM_SMEM);

    __half* gx;
    cudaGetSymbolAddress((void**)&gx, g_Xh);

    const int NX4 = MROWS * DMODEL / 4;
    cvt_x_h<<<(NX4 + 255) / 256, 256>>>(x, gx, NX4);
    transpose_wqkv_t<<<dim3(32, 2, 48), dim3(32, 8)>>>(Wq, Wk, Wv);
    transpose_wo_t  <<<dim3(32, 32),    dim3(32, 8)>>>(Wo);

    qkv_proj<<<dim3(MROWS / 128, 24), 256, GEMM_SMEM>>>(bq, bk, bv);
    attn_flash<<<dim3(SEQ / 128, BATCH * NH), 256, ATTN_SMEM>>>();
    out_proj<<<dim3(MROWS / 128, 8), 256, GEMM_SMEM>>>(bo, out);
}